// round 1
// baseline (speedup 1.0000x reference)
#include <cuda_runtime.h>

#define NROWS 100000
#define KK    27
#define CIN   64
#define COUT  128

// ---------------- scratch (static device allocations; no cudaMalloc) ----------------
__device__ float g_y[(size_t)NROWS * COUT];          // y1 then y2 (reused)
__device__ float g_h[(size_t)(NROWS + 1) * COUT];    // h1 with zero row at index NROWS
__device__ float g_part_sum[256 * COUT];
__device__ float g_part_sq [256 * COUT];
__device__ float g_bnA[2][COUT];
__device__ float g_bnB[2][COUT];

// ---------------- f32x2 helpers ----------------
__device__ __forceinline__ void ffma2(unsigned long long &acc, unsigned long long a,
                                      unsigned long long b) {
    asm("fma.rn.f32x2 %0, %1, %2, %0;" : "+l"(acc) : "l"(a), "l"(b));
}
__device__ __forceinline__ float f2lo(unsigned long long v) {
    return __uint_as_float((unsigned)(v & 0xffffffffull));
}
__device__ __forceinline__ float f2hi(unsigned long long v) {
    return __uint_as_float((unsigned)(v >> 32));
}

// ---------------- gather-GEMM conv kernel ----------------
// y[n,d] = sum_k sum_c x_pad[nbr[n,k], c] * W[k,c,d]
// Block: 128 rows x 128 cols, 256 threads, each thread 8x8 (rows packed as f32x2 pairs).
template <int C, bool PADDED>
__global__ void __launch_bounds__(256) conv_kernel(const float* __restrict__ xin,
                                                   const int*   __restrict__ nbr,
                                                   const float* __restrict__ W) {
    constexpr int LDA = 132;  // padded A-tile row stride (floats), keeps 16B alignment
    extern __shared__ char smem[];
    int*   s_idx = (int*)smem;                                   // [KK][128]
    float* sA    = (float*)(smem + KK * 128 * sizeof(int));      // [C][LDA]  (A^T: sA[c][r])
    float* sBd   = sA + C * LDA;                                 // [C][256]  (B duplicated)

    const int tid = threadIdx.x;
    const int r0  = blockIdx.x * 128;
    const float* src = PADDED ? (const float*)g_h : xin;

    // Load neighbor indices for this row tile (coalesced linear read).
    {
        const int tot = 128 * KK;
        int valid = NROWS - r0; if (valid > 128) valid = 128;
        for (int e = tid; e < tot; e += 256) {
            int r = e / KK, k = e - r * KK;
            int idx = (r < valid) ? nbr[(size_t)(r0 + r) * KK + k] : NROWS;
            s_idx[k * 128 + r] = idx;
        }
    }

    const int tx = tid & 15, ty = tid >> 4;
    const int tx4 = tx * 4, ty4 = ty * 4;

    unsigned long long acc[4][8];
#pragma unroll
    for (int i = 0; i < 4; ++i)
#pragma unroll
        for (int j = 0; j < 8; ++j) acc[i][j] = 0ull;

    for (int k = 0; k < KK; ++k) {
        __syncthreads();
        // ---- gather A (transpose into sA[c][r]) ----
        const int* idxk = &s_idx[k * 128];
        for (int e = tid; e < 128 * (C / 4); e += 256) {
            int r  = e & 127;
            int c4 = e >> 7;
            int idx = idxk[r];
            float4 v;
            if (!PADDED && idx >= NROWS) v = make_float4(0.f, 0.f, 0.f, 0.f);
            else                         v = *(const float4*)(src + (size_t)idx * C + c4 * 4);
            float* dst = &sA[(c4 * 4) * LDA + r];
            dst[0]       = v.x;
            dst[LDA]     = v.y;
            dst[2 * LDA] = v.z;
            dst[3 * LDA] = v.w;
        }
        // ---- load W[k] duplicated: sBd[c][2j] = sBd[c][2j+1] = W[k][c][j] ----
        const float2* Wk = (const float2*)(W + (size_t)k * C * COUT);
        for (int e = tid; e < C * (COUT / 2); e += 256) {
            float2 w = Wk[e];
            int c  = e >> 6;      // COUT/2 == 64
            int j2 = e & 63;
            *(float4*)&sBd[c * 256 + j2 * 4] = make_float4(w.x, w.x, w.y, w.y);
        }
        __syncthreads();
        // ---- FFMA2 mainloop ----
#pragma unroll 8
        for (int c = 0; c < C; ++c) {
            const float* Ar = &sA[c * LDA];
            ulonglong2 aLo = *(const ulonglong2*)(Ar + ty4);        // rows (ty4,ty4+1),(ty4+2,+3)
            ulonglong2 aHi = *(const ulonglong2*)(Ar + 64 + ty4);   // rows (+64 versions)
            const unsigned long long* Br = (const unsigned long long*)(sBd + c * 256);
            ulonglong2 p0 = *(const ulonglong2*)(Br + tx4);
            ulonglong2 p1 = *(const ulonglong2*)(Br + tx4 + 2);
            ulonglong2 p2 = *(const ulonglong2*)(Br + 64 + tx4);
            ulonglong2 p3 = *(const ulonglong2*)(Br + 66 + tx4);
            unsigned long long bb[8] = {p0.x, p0.y, p1.x, p1.y, p2.x, p2.y, p3.x, p3.y};
#pragma unroll
            for (int j = 0; j < 8; ++j) {
                ffma2(acc[0][j], aLo.x, bb[j]);
                ffma2(acc[1][j], aLo.y, bb[j]);
                ffma2(acc[2][j], aHi.x, bb[j]);
                ffma2(acc[3][j], aHi.y, bb[j]);
            }
        }
    }

    // ---- epilogue: unpack row pairs, write y ----
#pragma unroll
    for (int rp = 0; rp < 4; ++rp) {
        int rbase = ((rp >> 1) ? 64 : 0) + ty4 + (rp & 1) * 2;
#pragma unroll
        for (int half = 0; half < 2; ++half) {
            int row = r0 + rbase + half;
            if (row >= NROWS) continue;
            float4 v0, v1;
            if (half == 0) {
                v0 = make_float4(f2lo(acc[rp][0]), f2lo(acc[rp][1]), f2lo(acc[rp][2]), f2lo(acc[rp][3]));
                v1 = make_float4(f2lo(acc[rp][4]), f2lo(acc[rp][5]), f2lo(acc[rp][6]), f2lo(acc[rp][7]));
            } else {
                v0 = make_float4(f2hi(acc[rp][0]), f2hi(acc[rp][1]), f2hi(acc[rp][2]), f2hi(acc[rp][3]));
                v1 = make_float4(f2hi(acc[rp][4]), f2hi(acc[rp][5]), f2hi(acc[rp][6]), f2hi(acc[rp][7]));
            }
            *(float4*)&g_y[(size_t)row * COUT + tx4]      = v0;
            *(float4*)&g_y[(size_t)row * COUT + 64 + tx4] = v1;
        }
    }
}

// ---------------- BN statistics: deterministic 2-stage reduction ----------------
__global__ void stats_partial_kernel() {
    __shared__ float ssum[256], ssq[256];
    int tid = threadIdx.x;
    int c = tid & 127, half = tid >> 7;
    float s = 0.f, q = 0.f;
    for (int row = blockIdx.x * 2 + half; row < NROWS; row += gridDim.x * 2) {
        float v = g_y[(size_t)row * COUT + c];
        s += v; q += v * v;
    }
    ssum[tid] = s; ssq[tid] = q;
    __syncthreads();
    if (tid < 128) {
        g_part_sum[blockIdx.x * COUT + tid] = ssum[tid] + ssum[tid + 128];
        g_part_sq [blockIdx.x * COUT + tid] = ssq [tid] + ssq [tid + 128];
    }
}

__global__ void stats_final_kernel(int layer, const float* __restrict__ gamma,
                                   const float* __restrict__ beta) {
    int c = threadIdx.x;  // 128 threads
    float s = 0.f, q = 0.f;
    for (int b = 0; b < 256; ++b) {
        s += g_part_sum[b * COUT + c];
        q += g_part_sq [b * COUT + c];
    }
    float mu  = s / (float)NROWS;
    float var = q / (float)NROWS - mu * mu;
    float inv = rsqrtf(var + 1e-5f);
    float A = inv * gamma[c];
    g_bnA[layer][c] = A;
    g_bnB[layer][c] = beta[c] - mu * A;
}

// ---------------- h = relu(bn(y)); writes zero row at NROWS ----------------
__global__ void bn_apply_kernel() {
    size_t total = (size_t)(NROWS + 1) * (COUT / 4);
    for (size_t i = (size_t)blockIdx.x * blockDim.x + threadIdx.x; i < total;
         i += (size_t)gridDim.x * blockDim.x) {
        size_t row = i >> 5;                 // COUT/4 == 32
        int cb = (int)(i & 31) * 4;
        float4 o = make_float4(0.f, 0.f, 0.f, 0.f);
        if (row < NROWS) {
            float4 v = *(const float4*)&g_y[row * COUT + cb];
            float4 A = *(const float4*)&g_bnA[0][cb];
            float4 B = *(const float4*)&g_bnB[0][cb];
            o.x = fmaxf(fmaf(v.x, A.x, B.x), 0.f);
            o.y = fmaxf(fmaf(v.y, A.y, B.y), 0.f);
            o.z = fmaxf(fmaf(v.z, A.z, B.z), 0.f);
            o.w = fmaxf(fmaf(v.w, A.w, B.w), 0.f);
        }
        *(float4*)&g_h[row * COUT + cb] = o;
    }
}

// ---------------- final: out = relu(bn2(y2)) + x @ W_skip ----------------
__global__ void __launch_bounds__(256) final_kernel(const float* __restrict__ x,
                                                    const float* __restrict__ Wskip,
                                                    float* __restrict__ out) {
    __shared__ float sW[CIN * COUT];  // 32 KB, [k][c] layout
    __shared__ float sx[32 * CIN];    // 8 KB
    const int tid = threadIdx.x;
    const int r0 = blockIdx.x * 32;

    {
        const float4* W4 = (const float4*)Wskip;
        float4* sW4 = (float4*)sW;
        for (int e = tid; e < CIN * COUT / 4; e += 256) sW4[e] = W4[e];
        float4* sx4 = (float4*)sx;
        for (int e = tid; e < 32 * CIN / 4; e += 256) {
            int r = e >> 4, c4 = (e & 15) * 4;
            int row = r0 + r;
            sx4[e] = (row < NROWS) ? *(const float4*)(x + (size_t)row * CIN + c4)
                                   : make_float4(0.f, 0.f, 0.f, 0.f);
        }
    }
    __syncthreads();

    const int c = tid & 127, rh = tid >> 7;  // rh in {0,1}: rows rh*16..rh*16+15
    float id[16];
#pragma unroll
    for (int i = 0; i < 16; ++i) id[i] = 0.f;

#pragma unroll
    for (int kc = 0; kc < CIN / 8; ++kc) {
        float w[8];
#pragma unroll
        for (int i = 0; i < 8; ++i) w[i] = sW[(kc * 8 + i) * COUT + c];
#pragma unroll
        for (int rr = 0; rr < 16; ++rr) {
            int rl = rh * 16 + rr;
            float4 xa = *(const float4*)&sx[rl * CIN + kc * 8];
            float4 xb = *(const float4*)&sx[rl * CIN + kc * 8 + 4];
            float t = id[rr];
            t = fmaf(xa.x, w[0], t); t = fmaf(xa.y, w[1], t);
            t = fmaf(xa.z, w[2], t); t = fmaf(xa.w, w[3], t);
            t = fmaf(xb.x, w[4], t); t = fmaf(xb.y, w[5], t);
            t = fmaf(xb.z, w[6], t); t = fmaf(xb.w, w[7], t);
            id[rr] = t;
        }
    }

    const float A = g_bnA[1][c], B = g_bnB[1][c];
#pragma unroll
    for (int rr = 0; rr < 16; ++rr) {
        int row = r0 + rh * 16 + rr;
        if (row >= NROWS) continue;
        float v = g_y[(size_t)row * COUT + c];
        out[(size_t)row * COUT + c] = fmaxf(fmaf(v, A, B), 0.f) + id[rr];
    }
}

// ---------------- launch ----------------
extern "C" void kernel_launch(void* const* d_in, const int* in_sizes, int n_in,
                              void* d_out, int out_size) {
    const float* x      = (const float*)d_in[0];
    const int*   nbr    = (const int*)  d_in[1];
    const float* W1     = (const float*)d_in[2];
    const float* gamma1 = (const float*)d_in[3];
    const float* beta1  = (const float*)d_in[4];
    const float* W2     = (const float*)d_in[5];
    const float* gamma2 = (const float*)d_in[6];
    const float* beta2  = (const float*)d_in[7];
    const float* Wskip  = (const float*)d_in[8];
    float* out = (float*)d_out;

    const int grid = (NROWS + 127) / 128;  // 782
    const int smem1 = KK * 128 * 4 + 64  * 132 * 4 + 64  * 256 * 4;  //  80 KB
    const int smem2 = KK * 128 * 4 + 128 * 132 * 4 + 128 * 256 * 4;  // 208 KB

    cudaFuncSetAttribute(conv_kernel<64,  false>, cudaFuncAttributeMaxDynamicSharedMemorySize, smem1);
    cudaFuncSetAttribute(conv_kernel<128, true >, cudaFuncAttributeMaxDynamicSharedMemorySize, smem2);

    conv_kernel<64, false><<<grid, 256, smem1>>>(x, nbr, W1);
    stats_partial_kernel<<<256, 256>>>();
    stats_final_kernel<<<1, 128>>>(0, gamma1, beta1);
    bn_apply_kernel<<<1024, 256>>>();
    conv_kernel<128, true><<<grid, 256, smem2>>>(nullptr, nbr, W2);
    stats_partial_kernel<<<256, 256>>>();
    stats_final_kernel<<<1, 128>>>(1, gamma2, beta2);
    final_kernel<<<(NROWS + 31) / 32, 256>>>(x, Wskip, out);
}

// round 4
// speedup vs baseline: 3.8087x; 3.8087x over previous
#include <cuda_runtime.h>
#include <cuda_bf16.h>
#include <cstdint>

#define NROWS 100000
#define KK    27
#define CIN   64
#define COUT  128

// ---------------- scratch (static device globals; no cudaMalloc) ----------------
__device__ float g_y[(size_t)NROWS * COUT];          // conv output (reused both layers)
__device__ float g_h[(size_t)(NROWS + 1) * COUT];    // h1 with zero row at index NROWS
__device__ float g_part_sum[256 * COUT];
__device__ float g_part_sq [256 * COUT];
__device__ float g_bnA[2][COUT];
__device__ float g_bnB[2][COUT];
// Pre-split bf16 weights, laid out exactly as the smem B tile:
// per (k, chunk): hi[128][40] bf16 then lo[128][40] bf16  (10240 bf16 = 20480 B)
__device__ uint16_t g_Wt1[KK * 2 * 10240];   // conv1: C=64  -> 2 chunks/k
__device__ uint16_t g_Wt2[KK * 4 * 10240];   // conv2: C=128 -> 4 chunks/k

// ---------------- helpers ----------------
__device__ __forceinline__ uint32_t smem_to_u32(const void* p) {
    uint32_t a;
    asm("{ .reg .u64 t; cvta.to.shared.u64 t, %1; cvt.u32.u64 %0, t; }" : "=r"(a) : "l"(p));
    return a;
}
__device__ __forceinline__ uint32_t pack_bf16(float a, float b) {
    __nv_bfloat162 t = __floats2bfloat162_rn(a, b);
    return *(uint32_t*)&t;
}
__device__ __forceinline__ void split2(float x, float& h, float& l) {
    __nv_bfloat16 bh = __float2bfloat16_rn(x);
    h = __bfloat162float(bh);
    l = x - h;
}
#define LDMX4(r, addr) \
    asm volatile("ldmatrix.sync.aligned.m8n8.x4.shared.b16 {%0,%1,%2,%3}, [%4];" \
        : "=r"((r)[0]), "=r"((r)[1]), "=r"((r)[2]), "=r"((r)[3]) : "r"(addr))
#define MMA_BF16(c, a, b) \
    asm volatile("mma.sync.aligned.m16n8k16.row.col.f32.bf16.bf16.f32 " \
        "{%0,%1,%2,%3}, {%4,%5,%6,%7}, {%8,%9}, {%0,%1,%2,%3};" \
        : "+f"((c)[0]), "+f"((c)[1]), "+f"((c)[2]), "+f"((c)[3]) \
        : "r"((a)[0]), "r"((a)[1]), "r"((a)[2]), "r"((a)[3]), "r"((b)[0]), "r"((b)[1]))

// ---------------- weight prep: transpose + bf16 split into smem-tile layout ----------------
// W[k][c][d] -> tile(k, c>>5): hi[d][c&31] (row pad 40), then lo.
template <int C>
__global__ void prep_kernel(const float* __restrict__ W) {
    uint16_t* dst = (C == 64) ? g_Wt1 : g_Wt2;
    int t = blockIdx.x * blockDim.x + threadIdx.x;
    if (t >= KK * C * COUT) return;
    int d = t & 127;
    int c = (t >> 7) % C;
    int k = t / (C * COUT);
    float h, l; split2(W[t], h, l);
    int chunk = c >> 5, cl = c & 31;
    uint16_t* base = dst + (size_t)(k * (C / 32) + chunk) * 10240;
    __nv_bfloat16 bh = __float2bfloat16_rn(h);
    __nv_bfloat16 bl = __float2bfloat16_rn(l);
    base[d * 40 + cl]        = *(uint16_t*)&bh;
    base[5120 + d * 40 + cl] = *(uint16_t*)&bl;
}

// ---------------- gather-GEMM conv via mma.sync bf16 (3xBF16) ----------------
// Block: 128 rows x 128 cols, 8 warps (64x32 warp tiles). Chunks of 32 input channels.
static constexpr int SM_IDX = 0;                      // [KK][128] int
static constexpr int SM_AH  = KK * 128 * 4;           // 13824: [128][40] bf16
static constexpr int SM_AL  = SM_AH + 10240;          // 24064
static constexpr int SM_BH  = SM_AL + 10240;          // 34304: [128][40] bf16 (hi)
static constexpr int SM_BL  = SM_BH + 10240;          // 44544  (lo, contiguous after hi)
static constexpr int SM_TOT = SM_BL + 10240;          // 54784

template <int C, bool PADDED>
__global__ void __launch_bounds__(256, 2) conv_mma_kernel(const float* __restrict__ xin,
                                                          const int*   __restrict__ nbr,
                                                          const uint16_t* __restrict__ Wt) {
    extern __shared__ char smem[];
    const uint32_t su = smem_to_u32(smem);
    const int tid = threadIdx.x;
    const int wid = tid >> 5, lane = tid & 31;
    const int r0 = blockIdx.x * 128;
    const float* src = PADDED ? (const float*)g_h : xin;
    constexpr int CH_PER_K = C / 32;
    constexpr int NCH = KK * CH_PER_K;

    // ---- load neighbor indices [k][r] ----
    {
        int valid = NROWS - r0; if (valid > 128) valid = 128;
        int* s_idx = (int*)(smem + SM_IDX);
        for (int e = tid; e < 128 * KK; e += 256) {
            int r = e / KK, k = e - r * KK;
            s_idx[k * 128 + r] = (r < valid) ? nbr[(size_t)(r0 + r) * KK + k] : NROWS;
        }
    }
    __syncthreads();
    const int* s_idx = (const int*)(smem + SM_IDX);

    const int wr = wid & 1, wc = wid >> 1;
    // per-thread ldmatrix A base offset (bytes): row = wr*64 + (lane&15), col = (lane>>4)*8
    const uint32_t aoff = (uint32_t)((wr * 64 + (lane & 15)) * 80 + (lane >> 4) * 16);
    // per-thread B base offset: n = wc*32 + (lane>>2), k-byte = (lane&3)*4
    const uint32_t boff = (uint32_t)((wc * 32 + (lane >> 2)) * 80 + (lane & 3) * 4);

    float acc[4][4][4];
#pragma unroll
    for (int a = 0; a < 4; ++a)
#pragma unroll
        for (int b = 0; b < 4; ++b)
#pragma unroll
            for (int c = 0; c < 4; ++c) acc[a][b][c] = 0.f;

    for (int i = 0; i < NCH; ++i) {
        const int k  = i / CH_PER_K;
        const int c0 = (i % CH_PER_K) * 32;
        __syncthreads();
        // ---- gather + split A: 128 rows x 32 c ----
        const int* idxk = &s_idx[k * 128];
#pragma unroll
        for (int e = tid; e < 1024; e += 256) {
            int r = e >> 3, q = e & 7;
            int idx = idxk[r];
            float4 v;
            if (!PADDED && idx >= NROWS) v = make_float4(0.f, 0.f, 0.f, 0.f);
            else v = *(const float4*)(src + (size_t)idx * C + c0 + q * 4);
            float hx, lx, hy, ly, hz, lz, hw, lw;
            split2(v.x, hx, lx); split2(v.y, hy, ly);
            split2(v.z, hz, lz); split2(v.w, hw, lw);
            uint32_t off = (uint32_t)(r * 80 + q * 8);
            *(uint2*)(smem + SM_AH + off) = make_uint2(pack_bf16(hx, hy), pack_bf16(hz, hw));
            *(uint2*)(smem + SM_AL + off) = make_uint2(pack_bf16(lx, ly), pack_bf16(lz, lw));
        }
        // ---- copy pre-laid-out B (hi+lo contiguous, 20480 B) ----
        {
            const float4* bs = (const float4*)(Wt + (size_t)i * 10240);
            float4* bd = (float4*)(smem + SM_BH);
#pragma unroll
            for (int e = tid; e < 1280; e += 256) bd[e] = bs[e];
        }
        __syncthreads();

        // ---- MMA: 2 k-steps of 16 ----
#pragma unroll
        for (int ks = 0; ks < 2; ++ks) {
            const uint32_t kb = (uint32_t)(ks * 32);
            uint32_t ah[4][4], al[4][4], bh[4][2], bl[4][2];
#pragma unroll
            for (int mt = 0; mt < 4; ++mt) LDMX4(ah[mt], su + SM_AH + aoff + mt * 1280 + kb);
#pragma unroll
            for (int nt = 0; nt < 4; ++nt) {
                uint32_t o = SM_BH + boff + nt * 640 + kb;
                bh[nt][0] = *(const uint32_t*)(smem + o);
                bh[nt][1] = *(const uint32_t*)(smem + o + 16);
            }
#pragma unroll
            for (int mt = 0; mt < 4; ++mt)
#pragma unroll
                for (int nt = 0; nt < 4; ++nt) MMA_BF16(acc[mt][nt], ah[mt], bh[nt]);
#pragma unroll
            for (int nt = 0; nt < 4; ++nt) {
                uint32_t o = SM_BL + boff + nt * 640 + kb;
                bl[nt][0] = *(const uint32_t*)(smem + o);
                bl[nt][1] = *(const uint32_t*)(smem + o + 16);
            }
#pragma unroll
            for (int mt = 0; mt < 4; ++mt)
#pragma unroll
                for (int nt = 0; nt < 4; ++nt) MMA_BF16(acc[mt][nt], ah[mt], bl[nt]);
#pragma unroll
            for (int mt = 0; mt < 4; ++mt) LDMX4(al[mt], su + SM_AL + aoff + mt * 1280 + kb);
#pragma unroll
            for (int mt = 0; mt < 4; ++mt)
#pragma unroll
                for (int nt = 0; nt < 4; ++nt) MMA_BF16(acc[mt][nt], al[mt], bh[nt]);
        }
    }

    // ---- epilogue: write y ----
#pragma unroll
    for (int mt = 0; mt < 4; ++mt) {
        int row = r0 + wr * 64 + mt * 16 + (lane >> 2);
        int col = wc * 32 + (lane & 3) * 2;
#pragma unroll
        for (int nt = 0; nt < 4; ++nt) {
            if (row < NROWS)
                *(float2*)&g_y[(size_t)row * COUT + col + nt * 8] =
                    make_float2(acc[mt][nt][0], acc[mt][nt][1]);
            if (row + 8 < NROWS)
                *(float2*)&g_y[(size_t)(row + 8) * COUT + col + nt * 8] =
                    make_float2(acc[mt][nt][2], acc[mt][nt][3]);
        }
    }
}

// ---------------- BN statistics: deterministic 2-stage reduction ----------------
__global__ void stats_partial_kernel() {
    __shared__ float ssum[256], ssq[256];
    int tid = threadIdx.x;
    int c = tid & 127, half = tid >> 7;
    float s = 0.f, q = 0.f;
    for (int row = blockIdx.x * 2 + half; row < NROWS; row += gridDim.x * 2) {
        float v = g_y[(size_t)row * COUT + c];
        s += v; q += v * v;
    }
    ssum[tid] = s; ssq[tid] = q;
    __syncthreads();
    if (tid < 128) {
        g_part_sum[blockIdx.x * COUT + tid] = ssum[tid] + ssum[tid + 128];
        g_part_sq [blockIdx.x * COUT + tid] = ssq [tid] + ssq [tid + 128];
    }
}

__global__ void stats_final_kernel(int layer, const float* __restrict__ gamma,
                                   const float* __restrict__ beta) {
    int c = threadIdx.x;  // 128 threads
    float s = 0.f, q = 0.f;
    for (int b = 0; b < 256; ++b) {
        s += g_part_sum[b * COUT + c];
        q += g_part_sq [b * COUT + c];
    }
    float mu  = s / (float)NROWS;
    float var = q / (float)NROWS - mu * mu;
    float inv = rsqrtf(var + 1e-5f);
    float A = inv * gamma[c];
    g_bnA[layer][c] = A;
    g_bnB[layer][c] = beta[c] - mu * A;
}

// ---------------- h = relu(bn(y)); writes zero row at NROWS ----------------
__global__ void bn_apply_kernel() {
    size_t total = (size_t)(NROWS + 1) * (COUT / 4);
    for (size_t i = (size_t)blockIdx.x * blockDim.x + threadIdx.x; i < total;
         i += (size_t)gridDim.x * blockDim.x) {
        size_t row = i >> 5;
        int cb = (int)(i & 31) * 4;
        float4 o = make_float4(0.f, 0.f, 0.f, 0.f);
        if (row < NROWS) {
            float4 v = *(const float4*)&g_y[row * COUT + cb];
            float4 A = *(const float4*)&g_bnA[0][cb];
            float4 B = *(const float4*)&g_bnB[0][cb];
            o.x = fmaxf(fmaf(v.x, A.x, B.x), 0.f);
            o.y = fmaxf(fmaf(v.y, A.y, B.y), 0.f);
            o.z = fmaxf(fmaf(v.z, A.z, B.z), 0.f);
            o.w = fmaxf(fmaf(v.w, A.w, B.w), 0.f);
        }
        *(float4*)&g_h[row * COUT + cb] = o;
    }
}

// ---------------- final: out = relu(bn2(y2)) + x @ W_skip ----------------
__global__ void __launch_bounds__(256) final_kernel(const float* __restrict__ x,
                                                    const float* __restrict__ Wskip,
                                                    float* __restrict__ out) {
    __shared__ float sW[CIN * COUT];
    __shared__ float sx[32 * CIN];
    const int tid = threadIdx.x;
    const int r0 = blockIdx.x * 32;

    {
        const float4* W4 = (const float4*)Wskip;
        float4* sW4 = (float4*)sW;
        for (int e = tid; e < CIN * COUT / 4; e += 256) sW4[e] = W4[e];
        float4* sx4 = (float4*)sx;
        for (int e = tid; e < 32 * CIN / 4; e += 256) {
            int r = e >> 4, c4 = (e & 15) * 4;
            int row = r0 + r;
            sx4[e] = (row < NROWS) ? *(const float4*)(x + (size_t)row * CIN + c4)
                                   : make_float4(0.f, 0.f, 0.f, 0.f);
        }
    }
    __syncthreads();

    const int c = tid & 127, rh = tid >> 7;
    float id[16];
#pragma unroll
    for (int i = 0; i < 16; ++i) id[i] = 0.f;

#pragma unroll
    for (int kc = 0; kc < CIN / 8; ++kc) {
        float w[8];
#pragma unroll
        for (int i = 0; i < 8; ++i) w[i] = sW[(kc * 8 + i) * COUT + c];
#pragma unroll
        for (int rr = 0; rr < 16; ++rr) {
            int rl = rh * 16 + rr;
            float4 xa = *(const float4*)&sx[rl * CIN + kc * 8];
            float4 xb = *(const float4*)&sx[rl * CIN + kc * 8 + 4];
            float t = id[rr];
            t = fmaf(xa.x, w[0], t); t = fmaf(xa.y, w[1], t);
            t = fmaf(xa.z, w[2], t); t = fmaf(xa.w, w[3], t);
            t = fmaf(xb.x, w[4], t); t = fmaf(xb.y, w[5], t);
            t = fmaf(xb.z, w[6], t); t = fmaf(xb.w, w[7], t);
            id[rr] = t;
        }
    }

    const float A = g_bnA[1][c], B = g_bnB[1][c];
#pragma unroll
    for (int rr = 0; rr < 16; ++rr) {
        int row = r0 + rh * 16 + rr;
        if (row >= NROWS) continue;
        float v = g_y[(size_t)row * COUT + c];
        out[(size_t)row * COUT + c] = fmaxf(fmaf(v, A, B), 0.f) + id[rr];
    }
}

// ---------------- launch ----------------
extern "C" void kernel_launch(void* const* d_in, const int* in_sizes, int n_in,
                              void* d_out, int out_size) {
    const float* x      = (const float*)d_in[0];
    const int*   nbr    = (const int*)  d_in[1];
    const float* W1     = (const float*)d_in[2];
    const float* gamma1 = (const float*)d_in[3];
    const float* beta1  = (const float*)d_in[4];
    const float* W2     = (const float*)d_in[5];
    const float* gamma2 = (const float*)d_in[6];
    const float* beta2  = (const float*)d_in[7];
    const float* Wskip  = (const float*)d_in[8];
    float* out = (float*)d_out;

    cudaFuncSetAttribute(conv_mma_kernel<64,  false>, cudaFuncAttributeMaxDynamicSharedMemorySize, SM_TOT);
    cudaFuncSetAttribute(conv_mma_kernel<128, true >, cudaFuncAttributeMaxDynamicSharedMemorySize, SM_TOT);

    const int grid = (NROWS + 127) / 128;  // 782

    prep_kernel<64> <<<(KK * 64  * COUT + 255) / 256, 256>>>(W1);
    prep_kernel<128><<<(KK * 128 * COUT + 255) / 256, 256>>>(W2);

    uint16_t* wt1; cudaGetSymbolAddress((void**)&wt1, g_Wt1);
    uint16_t* wt2; cudaGetSymbolAddress((void**)&wt2, g_Wt2);

    conv_mma_kernel<64, false><<<grid, 256, SM_TOT>>>(x, nbr, wt1);
    stats_partial_kernel<<<256, 256>>>();
    stats_final_kernel<<<1, 128>>>(0, gamma1, beta1);
    bn_apply_kernel<<<1024, 256>>>();
    conv_mma_kernel<128, true><<<grid, 256, SM_TOT>>>(nullptr, nbr, wt2);
    stats_partial_kernel<<<256, 256>>>();
    stats_final_kernel<<<1, 128>>>(1, gamma2, beta2);
    final_kernel<<<(NROWS + 31) / 32, 256>>>(x, Wskip, out);
}

// round 5
// speedup vs baseline: 4.4567x; 1.1701x over previous
#include <cuda_runtime.h>
#include <cuda_bf16.h>
#include <cstdint>

#define NROWS 100000
#define KK    27
#define CIN   64
#define COUT  128
#define NBLK  391            // (NROWS+255)/256

// ---------------- scratch (static device globals; no cudaMalloc) ----------------
__device__ float g_y[(size_t)NROWS * COUT];          // conv1 output
__device__ float g_h[(size_t)NROWS * COUT];          // conv2 output
__device__ float g_psum[NBLK * COUT];
__device__ float g_psq [NBLK * COUT];
__device__ float g_msum[16 * COUT];
__device__ float g_msq [16 * COUT];
__device__ float g_bnA[2][COUT];
__device__ float g_bnB[2][COUT];
// Pre-split bf16 weights, laid out exactly as the smem B tile:
// per (k, chunk): hi[128][40] bf16 then lo[128][40] bf16  (10240 bf16 = 20480 B)
__device__ __align__(16) uint16_t g_Wt1[KK * 2 * 10240];   // conv1: C=64  -> 2 chunks/k
__device__ __align__(16) uint16_t g_Wt2[KK * 4 * 10240];   // conv2: C=128 -> 4 chunks/k

// ---------------- helpers ----------------
__device__ __forceinline__ uint32_t smem_to_u32(const void* p) {
    uint32_t a;
    asm("{ .reg .u64 t; cvta.to.shared.u64 t, %1; cvt.u32.u64 %0, t; }" : "=r"(a) : "l"(p));
    return a;
}
__device__ __forceinline__ uint32_t pack_bf16(float a, float b) {
    __nv_bfloat162 t = __floats2bfloat162_rn(a, b);
    return *(uint32_t*)&t;
}
__device__ __forceinline__ void split2(float x, float& h, float& l) {
    __nv_bfloat16 bh = __float2bfloat16_rn(x);
    h = __bfloat162float(bh);
    l = x - h;
}
__device__ __forceinline__ void cp16(uint32_t dst, const void* src) {
    asm volatile("cp.async.cg.shared.global [%0], [%1], 16;" :: "r"(dst), "l"(src));
}
#define CP_COMMIT() asm volatile("cp.async.commit_group;" ::: "memory")
#define CP_WAIT0()  asm volatile("cp.async.wait_group 0;"  ::: "memory")
#define LDMX4(r, addr) \
    asm volatile("ldmatrix.sync.aligned.m8n8.x4.shared.b16 {%0,%1,%2,%3}, [%4];" \
        : "=r"((r)[0]), "=r"((r)[1]), "=r"((r)[2]), "=r"((r)[3]) : "r"(addr))
#define MMA_BF16(c, a, b) \
    asm volatile("mma.sync.aligned.m16n8k16.row.col.f32.bf16.bf16.f32 " \
        "{%0,%1,%2,%3}, {%4,%5,%6,%7}, {%8,%9}, {%0,%1,%2,%3};" \
        : "+f"((c)[0]), "+f"((c)[1]), "+f"((c)[2]), "+f"((c)[3]) \
        : "r"((a)[0]), "r"((a)[1]), "r"((a)[2]), "r"((a)[3]), "r"((b)[0]), "r"((b)[1]))

// ---------------- weight prep: transpose + bf16 split into smem-tile layout ----------------
template <int C>
__global__ void prep_kernel(const float* __restrict__ W) {
    uint16_t* dst = (C == 64) ? g_Wt1 : g_Wt2;
    int t = blockIdx.x * blockDim.x + threadIdx.x;
    if (t >= KK * C * COUT) return;
    int d = t & 127;
    int c = (t >> 7) % C;
    int k = t / (C * COUT);
    float h, l; split2(W[t], h, l);
    int chunk = c >> 5, cl = c & 31;
    uint16_t* base = dst + (size_t)(k * (C / 32) + chunk) * 10240;
    __nv_bfloat16 bh = __float2bfloat16_rn(h);
    __nv_bfloat16 bl = __float2bfloat16_rn(l);
    base[d * 40 + cl]        = *(uint16_t*)&bh;
    base[5120 + d * 40 + cl] = *(uint16_t*)&bl;
}

// ---------------- gather-GEMM conv via mma.sync bf16 (3xBF16), pipelined ----------------
// Block: 256 rows x 128 cols, 16 warps (64x32 warp tiles), double-buffered smem stages.
// Fused: optional BN+ReLU on gather (conv2); BN statistics reduced in epilogue.
static constexpr int SM_IDX   = 0;                   // [KK][256] int = 27648
static constexpr int SM_BN    = 27648;               // 128+128 floats = 1024
static constexpr int SM_STAGE = 28672;               // 2 buffers x 61440
static constexpr int BUF_AH = 0, BUF_AL = 20480, BUF_B = 40960;  // B: hi then lo (20480)
static constexpr int BUF_STRIDE = 61440;
static constexpr int SM_TOT = SM_STAGE + 2 * BUF_STRIDE;         // 151552

template <int C, bool FUSE_BN>
__global__ void __launch_bounds__(512, 1) conv_mma_kernel(const float* __restrict__ xin,
                                                          const int*   __restrict__ nbr,
                                                          const uint16_t* __restrict__ Wt,
                                                          float* __restrict__ dst,
                                                          const float* __restrict__ bnA,
                                                          const float* __restrict__ bnB) {
    extern __shared__ char smem[];
    const uint32_t su = smem_to_u32(smem);
    const int tid = threadIdx.x;
    const int wid = tid >> 5, lane = tid & 31;
    const int r0 = blockIdx.x * 256;
    constexpr int CH_PER_K = C / 32;
    constexpr int NCH = KK * CH_PER_K;

    int* s_idx = (int*)(smem + SM_IDX);
    float* sBNA = (float*)(smem + SM_BN);
    float* sBNB = sBNA + 128;

    // ---- prologue: neighbor indices + bn table ----
    {
        int valid = NROWS - r0; if (valid > 256) valid = 256;
        for (int e = tid; e < 256 * KK; e += 512) {
            int r = e / KK, k = e - r * KK;
            s_idx[k * 256 + r] = (r < valid) ? nbr[(size_t)(r0 + r) * KK + k] : NROWS;
        }
        if (FUSE_BN && tid < 128) { sBNA[tid] = bnA[tid]; sBNB[tid] = bnB[tid]; }
    }
    __syncthreads();

    const int q  = tid & 7;          // column quad (constant per thread)
    const int rb = tid >> 3;         // row base 0..63

    const int wr = wid & 3, wc = wid >> 2;
    const uint32_t aoff = (uint32_t)((wr * 64 + (lane & 15)) * 80 + (lane >> 4) * 16);
    const uint32_t boff = (uint32_t)((wc * 32 + (lane >> 2)) * 80 + (lane & 3) * 4);

    float acc[4][4][4];
#pragma unroll
    for (int a = 0; a < 4; ++a)
#pragma unroll
        for (int b = 0; b < 4; ++b)
#pragma unroll
            for (int c2 = 0; c2 < 4; ++c2) acc[a][b][c2] = 0.f;

    float4 v[4];

    // stage helpers (lambdas keep register lifetimes tight)
    auto stageB = [&](int i, int buf) {
        uint32_t bdst = su + SM_STAGE + buf * BUF_STRIDE + BUF_B;
        const char* bsrc = (const char*)Wt + (size_t)i * 20480;
#pragma unroll
        for (int e = tid; e < 1280; e += 512) cp16(bdst + e * 16, bsrc + e * 16);
    };
    auto loadA = [&](int i) {
        const int k  = i / CH_PER_K;
        const int c0 = (i % CH_PER_K) * 32;
        const int* idxk = s_idx + k * 256;
        float4 A4, B4;
        if (FUSE_BN) {
            A4 = *(const float4*)&sBNA[c0 + q * 4];
            B4 = *(const float4*)&sBNB[c0 + q * 4];
        }
#pragma unroll
        for (int j = 0; j < 4; ++j) {
            int idx = idxk[rb + j * 64];
            if (idx >= NROWS) v[j] = make_float4(0.f, 0.f, 0.f, 0.f);
            else {
                float4 t = *(const float4*)(xin + (size_t)idx * C + c0 + q * 4);
                if (FUSE_BN) {
                    t.x = fmaxf(fmaf(t.x, A4.x, B4.x), 0.f);
                    t.y = fmaxf(fmaf(t.y, A4.y, B4.y), 0.f);
                    t.z = fmaxf(fmaf(t.z, A4.z, B4.z), 0.f);
                    t.w = fmaxf(fmaf(t.w, A4.w, B4.w), 0.f);
                }
                v[j] = t;
            }
        }
    };
    auto storeA = [&](int buf) {
        char* aH = smem + SM_STAGE + buf * BUF_STRIDE + BUF_AH;
        char* aL = smem + SM_STAGE + buf * BUF_STRIDE + BUF_AL;
#pragma unroll
        for (int j = 0; j < 4; ++j) {
            float hx, lx, hy, ly, hz, lz, hw, lw;
            split2(v[j].x, hx, lx); split2(v[j].y, hy, ly);
            split2(v[j].z, hz, lz); split2(v[j].w, hw, lw);
            uint32_t off = (uint32_t)((rb + j * 64) * 80 + q * 8);
            *(uint2*)(aH + off) = make_uint2(pack_bf16(hx, hy), pack_bf16(hz, hw));
            *(uint2*)(aL + off) = make_uint2(pack_bf16(lx, ly), pack_bf16(lz, lw));
        }
    };
    auto mmaChunk = [&](int buf) {
        uint32_t base = su + SM_STAGE + buf * BUF_STRIDE;
        const char* bbase = smem + SM_STAGE + buf * BUF_STRIDE + BUF_B;
#pragma unroll
        for (int ks = 0; ks < 2; ++ks) {
            const uint32_t kb = (uint32_t)(ks * 32);
            uint32_t a[4][4], b[4][2], b2[4][2];
#pragma unroll
            for (int mt = 0; mt < 4; ++mt) LDMX4(a[mt], base + BUF_AH + aoff + mt * 1280 + kb);
#pragma unroll
            for (int nt = 0; nt < 4; ++nt) {
                const char* o = bbase + boff + nt * 640 + kb;
                b[nt][0] = *(const uint32_t*)o;
                b[nt][1] = *(const uint32_t*)(o + 16);
            }
#pragma unroll
            for (int mt = 0; mt < 4; ++mt)
#pragma unroll
                for (int nt = 0; nt < 4; ++nt) MMA_BF16(acc[mt][nt], a[mt], b[nt]);
#pragma unroll
            for (int nt = 0; nt < 4; ++nt) {
                const char* o = bbase + 10240 + boff + nt * 640 + kb;
                b2[nt][0] = *(const uint32_t*)o;
                b2[nt][1] = *(const uint32_t*)(o + 16);
            }
#pragma unroll
            for (int mt = 0; mt < 4; ++mt)
#pragma unroll
                for (int nt = 0; nt < 4; ++nt) MMA_BF16(acc[mt][nt], a[mt], b2[nt]);
#pragma unroll
            for (int mt = 0; mt < 4; ++mt) LDMX4(a[mt], base + BUF_AL + aoff + mt * 1280 + kb);
#pragma unroll
            for (int mt = 0; mt < 4; ++mt)
#pragma unroll
                for (int nt = 0; nt < 4; ++nt) MMA_BF16(acc[mt][nt], a[mt], b[nt]);
        }
    };

    // ---- pipeline ----
    stageB(0, 0); CP_COMMIT();
    loadA(0); storeA(0);
    CP_WAIT0();
    __syncthreads();

    for (int i = 0; i < NCH; ++i) {
        const int buf = i & 1;
        const bool more = (i + 1 < NCH);
        if (more) { stageB(i + 1, buf ^ 1); CP_COMMIT(); loadA(i + 1); }
        mmaChunk(buf);
        if (more) { storeA(buf ^ 1); CP_WAIT0(); }
        __syncthreads();
    }

    // ---- epilogue: write y ----
#pragma unroll
    for (int mt = 0; mt < 4; ++mt) {
        int row = r0 + wr * 64 + mt * 16 + (lane >> 2);
        int col = wc * 32 + (lane & 3) * 2;
#pragma unroll
        for (int nt = 0; nt < 4; ++nt) {
            if (row < NROWS)
                *(float2*)&dst[(size_t)row * COUT + col + nt * 8] =
                    make_float2(acc[mt][nt][0], acc[mt][nt][1]);
            if (row + 8 < NROWS)
                *(float2*)&dst[(size_t)(row + 8) * COUT + col + nt * 8] =
                    make_float2(acc[mt][nt][2], acc[mt][nt][3]);
        }
    }

    // ---- fused BN statistics (per-CTA partial sums; zeros from sentinel rows are exact) ----
    {
        float* ssum = (float*)(smem + SM_STAGE);          // [4][128]
        float* ssq  = ssum + 512;                         // [4][128]
        float s[4][2], qq[4][2];
#pragma unroll
        for (int nt = 0; nt < 4; ++nt)
#pragma unroll
            for (int p = 0; p < 2; ++p) {
                float ss = 0.f, sq = 0.f;
#pragma unroll
                for (int mt = 0; mt < 4; ++mt) {
                    float a0 = acc[mt][nt][p], a1 = acc[mt][nt][p + 2];
                    ss += a0 + a1;
                    sq += a0 * a0 + a1 * a1;
                }
#pragma unroll
                for (int o = 4; o <= 16; o <<= 1) {
                    ss += __shfl_xor_sync(0xffffffffu, ss, o);
                    sq += __shfl_xor_sync(0xffffffffu, sq, o);
                }
                s[nt][p] = ss; qq[nt][p] = sq;
            }
        if (lane < 4) {
#pragma unroll
            for (int nt = 0; nt < 4; ++nt)
#pragma unroll
                for (int p = 0; p < 2; ++p) {
                    int col = wc * 32 + lane * 2 + nt * 8 + p;
                    ssum[wr * 128 + col] = s[nt][p];
                    ssq [wr * 128 + col] = qq[nt][p];
                }
        }
        __syncthreads();
        if (tid < 128) {
            float S = 0.f, Q = 0.f;
#pragma unroll
            for (int w = 0; w < 4; ++w) { S += ssum[w * 128 + tid]; Q += ssq[w * 128 + tid]; }
            g_psum[blockIdx.x * COUT + tid] = S;
            g_psq [blockIdx.x * COUT + tid] = Q;
        }
    }
}

// ---------------- stats reduction (deterministic two-stage) ----------------
__global__ void stats_mid_kernel() {
    int c = threadIdx.x;                 // 128
    int b0 = blockIdx.x;                 // 16
    float s = 0.f, q = 0.f;
    for (int b = b0; b < NBLK; b += 16) {
        s += g_psum[b * COUT + c];
        q += g_psq [b * COUT + c];
    }
    g_msum[b0 * COUT + c] = s;
    g_msq [b0 * COUT + c] = q;
}

__global__ void stats_final_kernel(int layer, const float* __restrict__ gamma,
                                   const float* __restrict__ beta) {
    int c = threadIdx.x;  // 128
    float s = 0.f, q = 0.f;
#pragma unroll
    for (int b = 0; b < 16; ++b) {
        s += g_msum[b * COUT + c];
        q += g_msq [b * COUT + c];
    }
    float mu  = s / (float)NROWS;
    float var = q / (float)NROWS - mu * mu;
    float inv = rsqrtf(var + 1e-5f);
    float A = inv * gamma[c];
    g_bnA[layer][c] = A;
    g_bnB[layer][c] = beta[c] - mu * A;
}

// ---------------- final: out = relu(bn2(y2)) + x @ W_skip ----------------
__global__ void __launch_bounds__(256) final_kernel(const float* __restrict__ x,
                                                    const float* __restrict__ Wskip,
                                                    float* __restrict__ out) {
    __shared__ float sW[CIN * COUT];
    __shared__ float sx[32 * CIN];
    const int tid = threadIdx.x;
    const int r0 = blockIdx.x * 32;

    {
        const float4* W4 = (const float4*)Wskip;
        float4* sW4 = (float4*)sW;
        for (int e = tid; e < CIN * COUT / 4; e += 256) sW4[e] = W4[e];
        float4* sx4 = (float4*)sx;
        for (int e = tid; e < 32 * CIN / 4; e += 256) {
            int r = e >> 4, c4 = (e & 15) * 4;
            int row = r0 + r;
            sx4[e] = (row < NROWS) ? *(const float4*)(x + (size_t)row * CIN + c4)
                                   : make_float4(0.f, 0.f, 0.f, 0.f);
        }
    }
    __syncthreads();

    const int c = tid & 127, rh = tid >> 7;
    float id[16];
#pragma unroll
    for (int i = 0; i < 16; ++i) id[i] = 0.f;

#pragma unroll
    for (int kc = 0; kc < CIN / 8; ++kc) {
        float w[8];
#pragma unroll
        for (int i = 0; i < 8; ++i) w[i] = sW[(kc * 8 + i) * COUT + c];
#pragma unroll
        for (int rr = 0; rr < 16; ++rr) {
            int rl = rh * 16 + rr;
            float4 xa = *(const float4*)&sx[rl * CIN + kc * 8];
            float4 xb = *(const float4*)&sx[rl * CIN + kc * 8 + 4];
            float t = id[rr];
            t = fmaf(xa.x, w[0], t); t = fmaf(xa.y, w[1], t);
            t = fmaf(xa.z, w[2], t); t = fmaf(xa.w, w[3], t);
            t = fmaf(xb.x, w[4], t); t = fmaf(xb.y, w[5], t);
            t = fmaf(xb.z, w[6], t); t = fmaf(xb.w, w[7], t);
            id[rr] = t;
        }
    }

    const float A = g_bnA[1][c], B = g_bnB[1][c];
#pragma unroll
    for (int rr = 0; rr < 16; ++rr) {
        int row = r0 + rh * 16 + rr;
        if (row >= NROWS) continue;
        float v = g_h[(size_t)row * COUT + c];
        out[(size_t)row * COUT + c] = fmaxf(fmaf(v, A, B), 0.f) + id[rr];
    }
}

// ---------------- launch ----------------
extern "C" void kernel_launch(void* const* d_in, const int* in_sizes, int n_in,
                              void* d_out, int out_size) {
    const float* x      = (const float*)d_in[0];
    const int*   nbr    = (const int*)  d_in[1];
    const float* W1     = (const float*)d_in[2];
    const float* gamma1 = (const float*)d_in[3];
    const float* beta1  = (const float*)d_in[4];
    const float* W2     = (const float*)d_in[5];
    const float* gamma2 = (const float*)d_in[6];
    const float* beta2  = (const float*)d_in[7];
    const float* Wskip  = (const float*)d_in[8];
    float* out = (float*)d_out;

    cudaFuncSetAttribute(conv_mma_kernel<64,  false>, cudaFuncAttributeMaxDynamicSharedMemorySize, SM_TOT);
    cudaFuncSetAttribute(conv_mma_kernel<128, true >, cudaFuncAttributeMaxDynamicSharedMemorySize, SM_TOT);

    uint16_t* wt1; cudaGetSymbolAddress((void**)&wt1, g_Wt1);
    uint16_t* wt2; cudaGetSymbolAddress((void**)&wt2, g_Wt2);
    float* y;  cudaGetSymbolAddress((void**)&y,  g_y);
    float* h;  cudaGetSymbolAddress((void**)&h,  g_h);
    float* bA; cudaGetSymbolAddress((void**)&bA, g_bnA);
    float* bB; cudaGetSymbolAddress((void**)&bB, g_bnB);

    prep_kernel<64> <<<(KK * 64  * COUT + 255) / 256, 256>>>(W1);
    prep_kernel<128><<<(KK * 128 * COUT + 255) / 256, 256>>>(W2);

    conv_mma_kernel<64, false><<<NBLK, 512, SM_TOT>>>(x, nbr, wt1, y, nullptr, nullptr);
    stats_mid_kernel<<<16, 128>>>();
    stats_final_kernel<<<1, 128>>>(0, gamma1, beta1);

    conv_mma_kernel<128, true><<<NBLK, 512, SM_TOT>>>(y, nbr, wt2, h, bA, bB);
    stats_mid_kernel<<<16, 128>>>();
    stats_final_kernel<<<1, 128>>>(1, gamma2, beta2);

    final_kernel<<<(NROWS + 31) / 32, 256>>>(x, Wskip, out);
}

// round 6
// speedup vs baseline: 6.0718x; 1.3624x over previous
#include <cuda_runtime.h>
#include <cuda_fp16.h>
#include <cstdint>

#define NROWS 100000
#define KK    27
#define CIN   64
#define COUT  128
#define NBLK  391            // (NROWS+255)/256

// ---------------- scratch (static device globals; no cudaMalloc) ----------------
__device__ float g_y[(size_t)NROWS * COUT];          // conv1 output
__device__ float g_h[(size_t)NROWS * COUT];          // conv2 output
__device__ float g_psum[NBLK * COUT];
__device__ float g_psq [NBLK * COUT];
__device__ float g_msum[16 * COUT];
__device__ float g_msq [16 * COUT];
__device__ float g_bnA[2][COUT];
__device__ float g_bnB[2][COUT];
// Pre-split fp16 weights, laid out exactly as the smem B tile:
// per (k, chunk): hi[128][40] half then lo[128][40] half  (10240 half = 20480 B)
__device__ __align__(16) uint16_t g_Wt1[KK * 2 * 10240];   // conv1: C=64  -> 2 chunks/k
__device__ __align__(16) uint16_t g_Wt2[KK * 4 * 10240];   // conv2: C=128 -> 4 chunks/k

// ---------------- helpers ----------------
__device__ __forceinline__ uint32_t smem_to_u32(const void* p) {
    uint32_t a;
    asm("{ .reg .u64 t; cvta.to.shared.u64 t, %1; cvt.u32.u64 %0, t; }" : "=r"(a) : "l"(p));
    return a;
}
__device__ __forceinline__ uint32_t pack_h2(float a, float b) {
    __half2 t = __floats2half2_rn(a, b);
    return *(uint32_t*)&t;
}
__device__ __forceinline__ void cp16(uint32_t dst, const void* src) {
    asm volatile("cp.async.cg.shared.global [%0], [%1], 16;" :: "r"(dst), "l"(src));
}
#define CP_COMMIT() asm volatile("cp.async.commit_group;" ::: "memory")
#define CP_WAIT0()  asm volatile("cp.async.wait_group 0;"  ::: "memory")
#define LDMX4(r, addr) \
    asm volatile("ldmatrix.sync.aligned.m8n8.x4.shared.b16 {%0,%1,%2,%3}, [%4];" \
        : "=r"((r)[0]), "=r"((r)[1]), "=r"((r)[2]), "=r"((r)[3]) : "r"(addr))
#define MMA_F16(c, a, b) \
    asm volatile("mma.sync.aligned.m16n8k16.row.col.f32.f16.f16.f32 " \
        "{%0,%1,%2,%3}, {%4,%5,%6,%7}, {%8,%9}, {%0,%1,%2,%3};" \
        : "+f"((c)[0]), "+f"((c)[1]), "+f"((c)[2]), "+f"((c)[3]) \
        : "r"((a)[0]), "r"((a)[1]), "r"((a)[2]), "r"((a)[3]), "r"((b)[0]), "r"((b)[1]))

// ---------------- weight prep: transpose + exact fp16 split into smem-tile layout ----------------
template <int C>
__global__ void prep_kernel(const float* __restrict__ W) {
    uint16_t* dst = (C == 64) ? g_Wt1 : g_Wt2;
    int t = blockIdx.x * blockDim.x + threadIdx.x;
    if (t >= KK * C * COUT) return;
    int d = t & 127;
    int c = (t >> 7) % C;
    int k = t / (C * COUT);
    float w = W[t];
    __half hh = __float2half_rn(w);
    __half hl = __float2half_rn(w - __half2float(hh));
    int chunk = c >> 5, cl = c & 31;
    uint16_t* base = dst + (size_t)(k * (C / 32) + chunk) * 10240;
    base[d * 40 + cl]        = *(uint16_t*)&hh;
    base[5120 + d * 40 + cl] = *(uint16_t*)&hl;
}

// ---------------- profiling landmark (keeps conv1 at launch slot 4) ----------------
__global__ void noop_kernel() {}

// ---------------- gather-GEMM conv via mma.sync fp16 (2-pass: Ah*Bh + Ah*Bl) ----------------
// Block: 256 rows x 128 cols, 16 warps (64x32 warp tiles), double-buffered smem stages.
// Fused: optional BN+ReLU on gather (conv2); BN statistics reduced in epilogue.
static constexpr int SM_IDX   = 0;                   // [KK][256] int = 27648
static constexpr int SM_BN    = 27648;               // 128+128 floats = 1024
static constexpr int SM_STAGE = 28672;               // 2 buffers x 40960
static constexpr int BUF_A = 0, BUF_B = 20480;       // A: 256x80B; B: hi(10240)+lo(10240)
static constexpr int BUF_STRIDE = 40960;
static constexpr int SM_TOT = SM_STAGE + 2 * BUF_STRIDE;   // 110592

template <int C, bool FUSE_BN>
__global__ void __launch_bounds__(512, 1) conv_mma_kernel(const float* __restrict__ xin,
                                                          const int*   __restrict__ nbr,
                                                          const uint16_t* __restrict__ Wt,
                                                          float* __restrict__ dst,
                                                          const float* __restrict__ bnA,
                                                          const float* __restrict__ bnB) {
    extern __shared__ char smem[];
    const uint32_t su = smem_to_u32(smem);
    const int tid = threadIdx.x;
    const int wid = tid >> 5, lane = tid & 31;
    const int r0 = blockIdx.x * 256;
    constexpr int CH_PER_K = C / 32;
    constexpr int NCH = KK * CH_PER_K;

    int* s_idx = (int*)(smem + SM_IDX);
    float* sBNA = (float*)(smem + SM_BN);
    float* sBNB = sBNA + 128;

    // ---- prologue: neighbor indices + bn table ----
    {
        int valid = NROWS - r0; if (valid > 256) valid = 256;
        for (int e = tid; e < 256 * KK; e += 512) {
            int r = e / KK, k = e - r * KK;
            s_idx[k * 256 + r] = (r < valid) ? nbr[(size_t)(r0 + r) * KK + k] : NROWS;
        }
        if (FUSE_BN && tid < 128) { sBNA[tid] = bnA[tid]; sBNB[tid] = bnB[tid]; }
    }
    __syncthreads();

    const int q  = tid & 7;          // column quad (constant per thread)
    const int rb = tid >> 3;         // row base 0..63

    const int wr = wid & 3, wc = wid >> 2;
    const uint32_t aoff = (uint32_t)((wr * 64 + (lane & 15)) * 80 + (lane >> 4) * 16);
    const uint32_t boff = (uint32_t)((wc * 32 + (lane >> 2)) * 80 + (lane & 3) * 4);

    float acc[4][4][4];
#pragma unroll
    for (int a = 0; a < 4; ++a)
#pragma unroll
        for (int b = 0; b < 4; ++b)
#pragma unroll
            for (int c2 = 0; c2 < 4; ++c2) acc[a][b][c2] = 0.f;

    float4 v[4];

    auto stageB = [&](int i, int buf) {
        uint32_t bdst = su + SM_STAGE + buf * BUF_STRIDE + BUF_B;
        const char* bsrc = (const char*)Wt + (size_t)i * 20480;
#pragma unroll
        for (int e = tid; e < 1280; e += 512) cp16(bdst + e * 16, bsrc + e * 16);
    };
    auto loadA = [&](int i) {
        const int k  = i / CH_PER_K;
        const int c0 = (i % CH_PER_K) * 32;
        const int* idxk = s_idx + k * 256;
        float4 A4, B4;
        if (FUSE_BN) {
            A4 = *(const float4*)&sBNA[c0 + q * 4];
            B4 = *(const float4*)&sBNB[c0 + q * 4];
        }
#pragma unroll
        for (int j = 0; j < 4; ++j) {
            int idx = idxk[rb + j * 64];
            if (idx >= NROWS) v[j] = make_float4(0.f, 0.f, 0.f, 0.f);
            else {
                float4 t = *(const float4*)(xin + (size_t)idx * C + c0 + q * 4);
                if (FUSE_BN) {
                    t.x = fmaxf(fmaf(t.x, A4.x, B4.x), 0.f);
                    t.y = fmaxf(fmaf(t.y, A4.y, B4.y), 0.f);
                    t.z = fmaxf(fmaf(t.z, A4.z, B4.z), 0.f);
                    t.w = fmaxf(fmaf(t.w, A4.w, B4.w), 0.f);
                }
                v[j] = t;
            }
        }
    };
    auto storeA = [&](int buf) {
        char* aT = smem + SM_STAGE + buf * BUF_STRIDE + BUF_A;
#pragma unroll
        for (int j = 0; j < 4; ++j) {
            uint32_t off = (uint32_t)((rb + j * 64) * 80 + q * 8);
            *(uint2*)(aT + off) = make_uint2(pack_h2(v[j].x, v[j].y), pack_h2(v[j].z, v[j].w));
        }
    };
    auto mmaChunk = [&](int buf) {
        uint32_t base = su + SM_STAGE + buf * BUF_STRIDE;
        const char* bbase = smem + SM_STAGE + buf * BUF_STRIDE + BUF_B;
#pragma unroll
        for (int ks = 0; ks < 2; ++ks) {
            const uint32_t kb = (uint32_t)(ks * 32);
            uint32_t a[4][4], b[4][2], b2[4][2];
#pragma unroll
            for (int mt = 0; mt < 4; ++mt) LDMX4(a[mt], base + BUF_A + aoff + mt * 1280 + kb);
#pragma unroll
            for (int nt = 0; nt < 4; ++nt) {
                const char* o = bbase + boff + nt * 640 + kb;
                b[nt][0] = *(const uint32_t*)o;
                b[nt][1] = *(const uint32_t*)(o + 16);
            }
#pragma unroll
            for (int mt = 0; mt < 4; ++mt)
#pragma unroll
                for (int nt = 0; nt < 4; ++nt) MMA_F16(acc[mt][nt], a[mt], b[nt]);
#pragma unroll
            for (int nt = 0; nt < 4; ++nt) {
                const char* o = bbase + 10240 + boff + nt * 640 + kb;
                b2[nt][0] = *(const uint32_t*)o;
                b2[nt][1] = *(const uint32_t*)(o + 16);
            }
#pragma unroll
            for (int mt = 0; mt < 4; ++mt)
#pragma unroll
                for (int nt = 0; nt < 4; ++nt) MMA_F16(acc[mt][nt], a[mt], b2[nt]);
        }
    };

    // ---- pipeline ----
    stageB(0, 0); CP_COMMIT();
    loadA(0); storeA(0);
    CP_WAIT0();
    __syncthreads();

    for (int i = 0; i < NCH; ++i) {
        const int buf = i & 1;
        const bool more = (i + 1 < NCH);
        if (more) { stageB(i + 1, buf ^ 1); CP_COMMIT(); loadA(i + 1); }
        mmaChunk(buf);
        if (more) { storeA(buf ^ 1); CP_WAIT0(); }
        __syncthreads();
    }

    // ---- epilogue: write y ----
#pragma unroll
    for (int mt = 0; mt < 4; ++mt) {
        int row = r0 + wr * 64 + mt * 16 + (lane >> 2);
        int col = wc * 32 + (lane & 3) * 2;
#pragma unroll
        for (int nt = 0; nt < 4; ++nt) {
            if (row < NROWS)
                *(float2*)&dst[(size_t)row * COUT + col + nt * 8] =
                    make_float2(acc[mt][nt][0], acc[mt][nt][1]);
            if (row + 8 < NROWS)
                *(float2*)&dst[(size_t)(row + 8) * COUT + col + nt * 8] =
                    make_float2(acc[mt][nt][2], acc[mt][nt][3]);
        }
    }

    // ---- fused BN statistics (per-CTA partial sums; zeros from sentinel rows are exact) ----
    {
        float* ssum = (float*)(smem + SM_STAGE);          // [4][128]
        float* ssq  = ssum + 512;                         // [4][128]
        float s[4][2], qq[4][2];
#pragma unroll
        for (int nt = 0; nt < 4; ++nt)
#pragma unroll
            for (int p = 0; p < 2; ++p) {
                float ss = 0.f, sq = 0.f;
#pragma unroll
                for (int mt = 0; mt < 4; ++mt) {
                    float a0 = acc[mt][nt][p], a1 = acc[mt][nt][p + 2];
                    ss += a0 + a1;
                    sq += a0 * a0 + a1 * a1;
                }
#pragma unroll
                for (int o = 4; o <= 16; o <<= 1) {
                    ss += __shfl_xor_sync(0xffffffffu, ss, o);
                    sq += __shfl_xor_sync(0xffffffffu, sq, o);
                }
                s[nt][p] = ss; qq[nt][p] = sq;
            }
        if (lane < 4) {
#pragma unroll
            for (int nt = 0; nt < 4; ++nt)
#pragma unroll
                for (int p = 0; p < 2; ++p) {
                    int col = wc * 32 + lane * 2 + nt * 8 + p;
                    ssum[wr * 128 + col] = s[nt][p];
                    ssq [wr * 128 + col] = qq[nt][p];
                }
        }
        __syncthreads();
        if (tid < 128) {
            float S = 0.f, Q = 0.f;
#pragma unroll
            for (int w = 0; w < 4; ++w) { S += ssum[w * 128 + tid]; Q += ssq[w * 128 + tid]; }
            g_psum[blockIdx.x * COUT + tid] = S;
            g_psq [blockIdx.x * COUT + tid] = Q;
        }
    }
}

// ---------------- stats reduction (deterministic two-stage) ----------------
__global__ void stats_mid_kernel() {
    int c = threadIdx.x;                 // 128
    int b0 = blockIdx.x;                 // 16
    float s = 0.f, q = 0.f;
    for (int b = b0; b < NBLK; b += 16) {
        s += g_psum[b * COUT + c];
        q += g_psq [b * COUT + c];
    }
    g_msum[b0 * COUT + c] = s;
    g_msq [b0 * COUT + c] = q;
}

__global__ void stats_final_kernel(int layer, const float* __restrict__ gamma,
                                   const float* __restrict__ beta) {
    int c = threadIdx.x;  // 128
    float s = 0.f, q = 0.f;
#pragma unroll
    for (int b = 0; b < 16; ++b) {
        s += g_msum[b * COUT + c];
        q += g_msq [b * COUT + c];
    }
    float mu  = s / (float)NROWS;
    float var = q / (float)NROWS - mu * mu;
    float inv = rsqrtf(var + 1e-5f);
    float A = inv * gamma[c];
    g_bnA[layer][c] = A;
    g_bnB[layer][c] = beta[c] - mu * A;
}

// ---------------- final: out = relu(bn2(y2)) + x @ W_skip ----------------
__global__ void __launch_bounds__(256) final_kernel(const float* __restrict__ x,
                                                    const float* __restrict__ Wskip,
                                                    float* __restrict__ out) {
    __shared__ float sW[CIN * COUT];
    __shared__ float sx[32 * CIN];
    const int tid = threadIdx.x;
    const int r0 = blockIdx.x * 32;

    {
        const float4* W4 = (const float4*)Wskip;
        float4* sW4 = (float4*)sW;
        for (int e = tid; e < CIN * COUT / 4; e += 256) sW4[e] = W4[e];
        float4* sx4 = (float4*)sx;
        for (int e = tid; e < 32 * CIN / 4; e += 256) {
            int r = e >> 4, c4 = (e & 15) * 4;
            int row = r0 + r;
            sx4[e] = (row < NROWS) ? *(const float4*)(x + (size_t)row * CIN + c4)
                                   : make_float4(0.f, 0.f, 0.f, 0.f);
        }
    }
    __syncthreads();

    const int c = tid & 127, rh = tid >> 7;
    float id[16];
#pragma unroll
    for (int i = 0; i < 16; ++i) id[i] = 0.f;

#pragma unroll
    for (int kc = 0; kc < CIN / 8; ++kc) {
        float w[8];
#pragma unroll
        for (int i = 0; i < 8; ++i) w[i] = sW[(kc * 8 + i) * COUT + c];
#pragma unroll
        for (int rr = 0; rr < 16; ++rr) {
            int rl = rh * 16 + rr;
            float4 xa = *(const float4*)&sx[rl * CIN + kc * 8];
            float4 xb = *(const float4*)&sx[rl * CIN + kc * 8 + 4];
            float t = id[rr];
            t = fmaf(xa.x, w[0], t); t = fmaf(xa.y, w[1], t);
            t = fmaf(xa.z, w[2], t); t = fmaf(xa.w, w[3], t);
            t = fmaf(xb.x, w[4], t); t = fmaf(xb.y, w[5], t);
            t = fmaf(xb.z, w[6], t); t = fmaf(xb.w, w[7], t);
            id[rr] = t;
        }
    }

    const float A = g_bnA[1][c], B = g_bnB[1][c];
#pragma unroll
    for (int rr = 0; rr < 16; ++rr) {
        int row = r0 + rh * 16 + rr;
        if (row >= NROWS) continue;
        float v = g_h[(size_t)row * COUT + c];
        out[(size_t)row * COUT + c] = fmaxf(fmaf(v, A, B), 0.f) + id[rr];
    }
}

// ---------------- launch ----------------
extern "C" void kernel_launch(void* const* d_in, const int* in_sizes, int n_in,
                              void* d_out, int out_size) {
    const float* x      = (const float*)d_in[0];
    const int*   nbr    = (const int*)  d_in[1];
    const float* W1     = (const float*)d_in[2];
    const float* gamma1 = (const float*)d_in[3];
    const float* beta1  = (const float*)d_in[4];
    const float* W2     = (const float*)d_in[5];
    const float* gamma2 = (const float*)d_in[6];
    const float* beta2  = (const float*)d_in[7];
    const float* Wskip  = (const float*)d_in[8];
    float* out = (float*)d_out;

    cudaFuncSetAttribute(conv_mma_kernel<64,  false>, cudaFuncAttributeMaxDynamicSharedMemorySize, SM_TOT);
    cudaFuncSetAttribute(conv_mma_kernel<128, true >, cudaFuncAttributeMaxDynamicSharedMemorySize, SM_TOT);

    uint16_t* wt1; cudaGetSymbolAddress((void**)&wt1, g_Wt1);
    uint16_t* wt2; cudaGetSymbolAddress((void**)&wt2, g_Wt2);
    float* y;  cudaGetSymbolAddress((void**)&y,  g_y);
    float* h;  cudaGetSymbolAddress((void**)&h,  g_h);
    float* bA; cudaGetSymbolAddress((void**)&bA, g_bnA);
    float* bB; cudaGetSymbolAddress((void**)&bB, g_bnB);

    prep_kernel<64> <<<(KK * 64  * COUT + 255) / 256, 256>>>(W1);      // launch 1
    prep_kernel<128><<<(KK * 128 * COUT + 255) / 256, 256>>>(W2);      // launch 2
    noop_kernel<<<1, 32>>>();                                          // launch 3 (profiling landmark)

    conv_mma_kernel<64, false><<<NBLK, 512, SM_TOT>>>(x, nbr, wt1, y, nullptr, nullptr);  // launch 4
    stats_mid_kernel<<<16, 128>>>();
    stats_final_kernel<<<1, 128>>>(0, gamma1, beta1);

    conv_mma_kernel<128, true><<<NBLK, 512, SM_TOT>>>(y, nbr, wt2, h, bA, bB);
    stats_mid_kernel<<<16, 128>>>();
    stats_final_kernel<<<1, 128>>>(1, gamma2, beta2);

    final_kernel<<<(NROWS + 31) / 32, 256>>>(x, Wskip, out);
}

// round 8
// speedup vs baseline: 9.3351x; 1.5374x over previous
#include <cuda_runtime.h>
#include <cuda_fp16.h>
#include <cstdint>

#define NROWS 100000
#define KK    27
#define CIN   64
#define COUT  128
#define NBLK  391            // (NROWS+255)/256

// ---------------- scratch (static device globals; no cudaMalloc) ----------------
__device__ float g_y[(size_t)NROWS * COUT];          // conv1 output
__device__ float g_h[(size_t)NROWS * COUT];          // conv2 output
__device__ float g_psum[NBLK * COUT];
__device__ float g_psq [NBLK * COUT];
__device__ float g_msum[16 * COUT];
__device__ float g_msq [16 * COUT];
__device__ float g_bnA[2][COUT];
__device__ float g_bnB[2][COUT];
// fp16 weights laid out as the smem B tile: per (k, 64c-chunk): [d=128][72] half (18432 B)
__device__ __align__(16) uint16_t g_Wt1[KK * 1 * 9216];   // conv1: C=64  -> 1 chunk/k
__device__ __align__(16) uint16_t g_Wt2[KK * 2 * 9216];   // conv2: C=128 -> 2 chunks/k

// ---------------- helpers ----------------
__device__ __forceinline__ uint32_t smem_to_u32(const void* p) {
    uint32_t a;
    asm("{ .reg .u64 t; cvta.to.shared.u64 t, %1; cvt.u32.u64 %0, t; }" : "=r"(a) : "l"(p));
    return a;
}
__device__ __forceinline__ uint32_t pack_h2(float a, float b) {
    __half2 t = __floats2half2_rn(a, b);
    return *(uint32_t*)&t;
}
__device__ __forceinline__ void cp16(uint32_t dst, const void* src) {
    asm volatile("cp.async.cg.shared.global [%0], [%1], 16;" :: "r"(dst), "l"(src));
}
#define CP_COMMIT() asm volatile("cp.async.commit_group;" ::: "memory")
#define CP_WAIT0()  asm volatile("cp.async.wait_group 0;"  ::: "memory")
#define LDMX4(r, addr) \
    asm volatile("ldmatrix.sync.aligned.m8n8.x4.shared.b16 {%0,%1,%2,%3}, [%4];" \
        : "=r"((r)[0]), "=r"((r)[1]), "=r"((r)[2]), "=r"((r)[3]) : "r"(addr))
#define MMA_F16(c, a, b) \
    asm volatile("mma.sync.aligned.m16n8k16.row.col.f32.f16.f16.f32 " \
        "{%0,%1,%2,%3}, {%4,%5,%6,%7}, {%8,%9}, {%0,%1,%2,%3};" \
        : "+f"((c)[0]), "+f"((c)[1]), "+f"((c)[2]), "+f"((c)[3]) \
        : "r"((a)[0]), "r"((a)[1]), "r"((a)[2]), "r"((a)[3]), "r"((b)[0]), "r"((b)[1]))

// ---------------- weight prep: transpose to smem-tile layout, fp16 ----------------
template <int C>
__global__ void prep_kernel(const float* __restrict__ W) {
    uint16_t* dst = (C == 64) ? g_Wt1 : g_Wt2;
    int t = blockIdx.x * blockDim.x + threadIdx.x;
    if (t >= KK * C * COUT) return;
    int d = t & 127;
    int c = (t >> 7) % C;
    int k = t / (C * COUT);
    __half hh = __float2half_rn(W[t]);
    int chunk = c >> 6, cl = c & 63;
    uint16_t* base = dst + (size_t)(k * (C / 64) + chunk) * 9216;
    base[d * 72 + cl] = *(uint16_t*)&hh;
}

// ---------------- profiling landmark (keeps conv1 at launch slot 4) ----------------
__global__ void noop_kernel() {}

// ---------------- gather-GEMM conv via mma.sync fp16 (single pass, 64-wide k chunks) ---
// Block: 256 rows x 128 cols, 16 warps (64x32 warp tiles), double-buffered smem stages.
// A staged in two 32-channel halves to keep the register prefetch small.
static constexpr int SM_IDX   = 0;                   // [KK][256] int = 27648
static constexpr int SM_BN    = 27648;               // 128+128 floats = 1024
static constexpr int SM_STAGE = 28672;
static constexpr int BUF_A = 0;                      // 256 rows x 144 B = 36864
static constexpr int BUF_B = 36864;                  // 128 x 144 B = 18432
static constexpr int BUF_STRIDE = 55296;
static constexpr int SM_TOT = SM_STAGE + 2 * BUF_STRIDE;   // 139264

template <int C, bool FUSE_BN>
__global__ void __launch_bounds__(512, 1) conv_mma_kernel(const float* __restrict__ xin,
                                                          const int*   __restrict__ nbr,
                                                          const uint16_t* __restrict__ Wt,
                                                          float* __restrict__ dst,
                                                          const float* __restrict__ bnA,
                                                          const float* __restrict__ bnB) {
    extern __shared__ char smem[];
    const uint32_t su = smem_to_u32(smem);
    const int tid = threadIdx.x;
    const int wid = tid >> 5, lane = tid & 31;
    const int r0 = blockIdx.x * 256;
    constexpr int CH_PER_K = C / 64;
    constexpr int NCH = KK * CH_PER_K;

    int* s_idx = (int*)(smem + SM_IDX);
    float* sBNA = (float*)(smem + SM_BN);
    float* sBNB = sBNA + 128;

    // ---- prologue: neighbor indices + bn table ----
    {
        int valid = NROWS - r0; if (valid > 256) valid = 256;
        for (int e = tid; e < 256 * KK; e += 512) {
            int r = e / KK, k = e - r * KK;
            s_idx[k * 256 + r] = (r < valid) ? nbr[(size_t)(r0 + r) * KK + k] : NROWS;
        }
        if (FUSE_BN && tid < 128) { sBNA[tid] = bnA[tid]; sBNB[tid] = bnB[tid]; }
    }
    __syncthreads();

    const int q  = tid & 7;          // 16B slot within a 32-channel half
    const int rb = tid >> 3;         // row base 0..63

    const int wr = wid & 3, wc = wid >> 2;
    const uint32_t aoff = (uint32_t)((wr * 64 + (lane & 15)) * 144 + (lane >> 4) * 16);
    const uint32_t boff = (uint32_t)((wc * 32 + (lane >> 2)) * 144 + (lane & 3) * 4);

    float acc[4][4][4];
#pragma unroll
    for (int a = 0; a < 4; ++a)
#pragma unroll
        for (int b = 0; b < 4; ++b)
#pragma unroll
            for (int c2 = 0; c2 < 4; ++c2) acc[a][b][c2] = 0.f;

    float4 v[4];

    auto stageB = [&](int i, int buf) {
        uint32_t bdst = su + SM_STAGE + buf * BUF_STRIDE + BUF_B;
        const char* bsrc = (const char*)Wt + (size_t)i * 18432;
#pragma unroll
        for (int e = tid; e < 1152; e += 512) cp16(bdst + e * 16, bsrc + e * 16);
    };
    auto loadA = [&](int i, int half) {
        const int k  = i / CH_PER_K;
        const int c0 = (i % CH_PER_K) * 64 + half * 32;
        const int* idxk = s_idx + k * 256;
        float4 A4, B4;
        if (FUSE_BN) {
            A4 = *(const float4*)&sBNA[c0 + q * 4];
            B4 = *(const float4*)&sBNB[c0 + q * 4];
        }
#pragma unroll
        for (int j = 0; j < 4; ++j) {
            int idx = idxk[rb + j * 64];
            if (idx >= NROWS) v[j] = make_float4(0.f, 0.f, 0.f, 0.f);
            else {
                float4 t = *(const float4*)(xin + (size_t)idx * C + c0 + q * 4);
                if (FUSE_BN) {
                    t.x = fmaxf(fmaf(t.x, A4.x, B4.x), 0.f);
                    t.y = fmaxf(fmaf(t.y, A4.y, B4.y), 0.f);
                    t.z = fmaxf(fmaf(t.z, A4.z, B4.z), 0.f);
                    t.w = fmaxf(fmaf(t.w, A4.w, B4.w), 0.f);
                }
                v[j] = t;
            }
        }
    };
    auto storeA = [&](int buf, int half) {
        char* aT = smem + SM_STAGE + buf * BUF_STRIDE + BUF_A;
#pragma unroll
        for (int j = 0; j < 4; ++j) {
            uint32_t off = (uint32_t)((rb + j * 64) * 144 + half * 64 + q * 8);
            *(uint2*)(aT + off) = make_uint2(pack_h2(v[j].x, v[j].y), pack_h2(v[j].z, v[j].w));
        }
    };
    auto mmaHalf = [&](int buf, int h) {
        uint32_t base = su + SM_STAGE + buf * BUF_STRIDE;
        const char* bbase = smem + SM_STAGE + buf * BUF_STRIDE + BUF_B;
#pragma unroll
        for (int ks = 0; ks < 2; ++ks) {
            const uint32_t kb = (uint32_t)((h * 2 + ks) * 32);
            uint32_t a[4][4], b[4][2];
#pragma unroll
            for (int mt = 0; mt < 4; ++mt) LDMX4(a[mt], base + BUF_A + aoff + mt * 2304 + kb);
#pragma unroll
            for (int nt = 0; nt < 4; ++nt) {
                const char* o = bbase + boff + nt * 1152 + kb;
                b[nt][0] = *(const uint32_t*)o;
                b[nt][1] = *(const uint32_t*)(o + 16);
            }
#pragma unroll
            for (int mt = 0; mt < 4; ++mt)
#pragma unroll
                for (int nt = 0; nt < 4; ++nt) MMA_F16(acc[mt][nt], a[mt], b[nt]);
        }
    };

    // ---- pipeline ----
    stageB(0, 0); CP_COMMIT();
    loadA(0, 0); storeA(0, 0);
    loadA(0, 1); storeA(0, 1);
    CP_WAIT0();
    __syncthreads();

    for (int i = 0; i < NCH; ++i) {
        const int buf = i & 1;
        const bool more = (i + 1 < NCH);
        if (more) { stageB(i + 1, buf ^ 1); CP_COMMIT(); loadA(i + 1, 0); }
        mmaHalf(buf, 0);
        if (more) { storeA(buf ^ 1, 0); loadA(i + 1, 1); }
        mmaHalf(buf, 1);
        if (more) { storeA(buf ^ 1, 1); CP_WAIT0(); }
        __syncthreads();
    }

    // ---- epilogue: write y ----
#pragma unroll
    for (int mt = 0; mt < 4; ++mt) {
        int row = r0 + wr * 64 + mt * 16 + (lane >> 2);
        int col = wc * 32 + (lane & 3) * 2;
#pragma unroll
        for (int nt = 0; nt < 4; ++nt) {
            if (row < NROWS)
                *(float2*)&dst[(size_t)row * COUT + col + nt * 8] =
                    make_float2(acc[mt][nt][0], acc[mt][nt][1]);
            if (row + 8 < NROWS)
                *(float2*)&dst[(size_t)(row + 8) * COUT + col + nt * 8] =
                    make_float2(acc[mt][nt][2], acc[mt][nt][3]);
        }
    }

    // ---- fused BN statistics (per-CTA partial sums; zeros from sentinel rows are exact) ----
    {
        float* ssum = (float*)(smem + SM_STAGE);          // [4][128]
        float* ssq  = ssum + 512;                         // [4][128]
        float s[4][2], qq[4][2];
#pragma unroll
        for (int nt = 0; nt < 4; ++nt)
#pragma unroll
            for (int p = 0; p < 2; ++p) {
                float ss = 0.f, sq = 0.f;
#pragma unroll
                for (int mt = 0; mt < 4; ++mt) {
                    float a0 = acc[mt][nt][p], a1 = acc[mt][nt][p + 2];
                    ss += a0 + a1;
                    sq += a0 * a0 + a1 * a1;
                }
#pragma unroll
                for (int o = 4; o <= 16; o <<= 1) {
                    ss += __shfl_xor_sync(0xffffffffu, ss, o);
                    sq += __shfl_xor_sync(0xffffffffu, sq, o);
                }
                s[nt][p] = ss; qq[nt][p] = sq;
            }
        if (lane < 4) {
#pragma unroll
            for (int nt = 0; nt < 4; ++nt)
#pragma unroll
                for (int p = 0; p < 2; ++p) {
                    int col = wc * 32 + lane * 2 + nt * 8 + p;
                    ssum[wr * 128 + col] = s[nt][p];
                    ssq [wr * 128 + col] = qq[nt][p];
                }
        }
        __syncthreads();
        if (tid < 128) {
            float S = 0.f, Q = 0.f;
#pragma unroll
            for (int w = 0; w < 4; ++w) { S += ssum[w * 128 + tid]; Q += ssq[w * 128 + tid]; }
            g_psum[blockIdx.x * COUT + tid] = S;
            g_psq [blockIdx.x * COUT + tid] = Q;
        }
    }
}

// ---------------- stats reduction (deterministic two-stage) ----------------
__global__ void stats_mid_kernel() {
    int c = threadIdx.x;                 // 128
    int b0 = blockIdx.x;                 // 16
    float s = 0.f, q = 0.f;
    for (int b = b0; b < NBLK; b += 16) {
        s += g_psum[b * COUT + c];
        q += g_psq [b * COUT + c];
    }
    g_msum[b0 * COUT + c] = s;
    g_msq [b0 * COUT + c] = q;
}

__global__ void stats_final_kernel(int layer, const float* __restrict__ gamma,
                                   const float* __restrict__ beta) {
    int c = threadIdx.x;  // 128
    float s = 0.f, q = 0.f;
#pragma unroll
    for (int b = 0; b < 16; ++b) {
        s += g_msum[b * COUT + c];
        q += g_msq [b * COUT + c];
    }
    float mu  = s / (float)NROWS;
    float var = q / (float)NROWS - mu * mu;
    float inv = rsqrtf(var + 1e-5f);
    float A = inv * gamma[c];
    g_bnA[layer][c] = A;
    g_bnB[layer][c] = beta[c] - mu * A;
}

// ---------------- final: out = relu(bn2(y2)) + x @ W_skip ----------------
__global__ void __launch_bounds__(256) final_kernel(const float* __restrict__ x,
                                                    const float* __restrict__ Wskip,
                                                    float* __restrict__ out) {
    __shared__ float sW[CIN * COUT];
    __shared__ float sx[32 * CIN];
    const int tid = threadIdx.x;
    const int r0 = blockIdx.x * 32;

    {
        const float4* W4 = (const float4*)Wskip;
        float4* sW4 = (float4*)sW;
        for (int e = tid; e < CIN * COUT / 4; e += 256) sW4[e] = W4[e];
        float4* sx4 = (float4*)sx;
        for (int e = tid; e < 32 * CIN / 4; e += 256) {
            int r = e >> 4, c4 = (e & 15) * 4;
            int row = r0 + r;
            sx4[e] = (row < NROWS) ? *(const float4*)(x + (size_t)row * CIN + c4)
                                   : make_float4(0.f, 0.f, 0.f, 0.f);
        }
    }
    __syncthreads();

    const int c = tid & 127, rh = tid >> 7;
    float id[16];
#pragma unroll
    for (int i = 0; i < 16; ++i) id[i] = 0.f;

#pragma unroll
    for (int kc = 0; kc < CIN / 8; ++kc) {
        float w[8];
#pragma unroll
        for (int i = 0; i < 8; ++i) w[i] = sW[(kc * 8 + i) * COUT + c];
#pragma unroll
        for (int rr = 0; rr < 16; ++rr) {
            int rl = rh * 16 + rr;
            float4 xa = *(const float4*)&sx[rl * CIN + kc * 8];
            float4 xb = *(const float4*)&sx[rl * CIN + kc * 8 + 4];
            float t = id[rr];
            t = fmaf(xa.x, w[0], t); t = fmaf(xa.y, w[1], t);
            t = fmaf(xa.z, w[2], t); t = fmaf(xa.w, w[3], t);
            t = fmaf(xb.x, w[4], t); t = fmaf(xb.y, w[5], t);
            t = fmaf(xb.z, w[6], t); t = fmaf(xb.w, w[7], t);
            id[rr] = t;
        }
    }

    const float A = g_bnA[1][c], B = g_bnB[1][c];
#pragma unroll
    for (int rr = 0; rr < 16; ++rr) {
        int row = r0 + rh * 16 + rr;
        if (row >= NROWS) continue;
        float v = g_h[(size_t)row * COUT + c];
        out[(size_t)row * COUT + c] = fmaxf(fmaf(v, A, B), 0.f) + id[rr];
    }
}

// ---------------- launch ----------------
extern "C" void kernel_launch(void* const* d_in, const int* in_sizes, int n_in,
                              void* d_out, int out_size) {
    const float* x      = (const float*)d_in[0];
    const int*   nbr    = (const int*)  d_in[1];
    const float* W1     = (const float*)d_in[2];
    const float* gamma1 = (const float*)d_in[3];
    const float* beta1  = (const float*)d_in[4];
    const float* W2     = (const float*)d_in[5];
    const float* gamma2 = (const float*)d_in[6];
    const float* beta2  = (const float*)d_in[7];
    const float* Wskip  = (const float*)d_in[8];
    float* out = (float*)d_out;

    cudaFuncSetAttribute(conv_mma_kernel<64,  false>, cudaFuncAttributeMaxDynamicSharedMemorySize, SM_TOT);
    cudaFuncSetAttribute(conv_mma_kernel<128, true >, cudaFuncAttributeMaxDynamicSharedMemorySize, SM_TOT);

    uint16_t* wt1; cudaGetSymbolAddress((void**)&wt1, g_Wt1);
    uint16_t* wt2; cudaGetSymbolAddress((void**)&wt2, g_Wt2);
    float* y;  cudaGetSymbolAddress((void**)&y,  g_y);
    float* h;  cudaGetSymbolAddress((void**)&h,  g_h);
    float* bA; cudaGetSymbolAddress((void**)&bA, g_bnA);
    float* bB; cudaGetSymbolAddress((void**)&bB, g_bnB);

    prep_kernel<64> <<<(KK * 64  * COUT + 255) / 256, 256>>>(W1);      // launch 1
    prep_kernel<128><<<(KK * 128 * COUT + 255) / 256, 256>>>(W2);      // launch 2
    noop_kernel<<<1, 32>>>();                                          // launch 3 (landmark)

    conv_mma_kernel<64, false><<<NBLK, 512, SM_TOT>>>(x, nbr, wt1, y, nullptr, nullptr);  // launch 4
    stats_mid_kernel<<<16, 128>>>();
    stats_final_kernel<<<1, 128>>>(0, gamma1, beta1);

    conv_mma_kernel<128, true><<<NBLK, 512, SM_TOT>>>(y, nbr, wt2, h, bA, bB);
    stats_mid_kernel<<<16, 128>>>();
    stats_final_kernel<<<1, 128>>>(1, gamma2, beta2);

    final_kernel<<<(NROWS + 31) / 32, 256>>>(x, Wskip, out);
}

// round 9
// speedup vs baseline: 10.7784x; 1.1546x over previous
#include <cuda_runtime.h>
#include <cuda_fp16.h>
#include <cstdint>

#define NROWS 100000
#define KK    27
#define CIN   64
#define COUT  128
#define NBLK  782            // (NROWS+127)/128

// ---------------- scratch (static device globals; no cudaMalloc) ----------------
__device__ float g_y[(size_t)NROWS * COUT];              // conv1 output (fp32)
__device__ float g_h[(size_t)NROWS * COUT];              // conv2 output (fp32)
__device__ __align__(16) __half g_h16[(size_t)(NROWS + 1) * COUT];  // bn1(y) fp16, zero sentinel row
__device__ float g_psum[NBLK * COUT];
__device__ float g_psq [NBLK * COUT];
__device__ float g_msum[16 * COUT];
__device__ float g_msq [16 * COUT];
__device__ float g_bnA[2][COUT];
__device__ float g_bnB[2][COUT];
// fp16 weights laid out as the smem B tile: per (k, 64c-chunk): [d=128][72] half (18432 B)
__device__ __align__(16) uint16_t g_Wt1[KK * 1 * 9216];   // conv1: C=64  -> 1 chunk/k
__device__ __align__(16) uint16_t g_Wt2[KK * 2 * 9216];   // conv2: C=128 -> 2 chunks/k

// ---------------- helpers ----------------
__device__ __forceinline__ uint32_t smem_to_u32(const void* p) {
    uint32_t a;
    asm("{ .reg .u64 t; cvta.to.shared.u64 t, %1; cvt.u32.u64 %0, t; }" : "=r"(a) : "l"(p));
    return a;
}
__device__ __forceinline__ uint32_t pack_h2(float a, float b) {
    __half2 t = __floats2half2_rn(a, b);
    return *(uint32_t*)&t;
}
__device__ __forceinline__ void cp16(uint32_t dst, const void* src) {
    asm volatile("cp.async.cg.shared.global [%0], [%1], 16;" :: "r"(dst), "l"(src));
}
#define CP_COMMIT() asm volatile("cp.async.commit_group;" ::: "memory")
#define CP_WAIT0()  asm volatile("cp.async.wait_group 0;"  ::: "memory")
#define LDMX4(r, addr) \
    asm volatile("ldmatrix.sync.aligned.m8n8.x4.shared.b16 {%0,%1,%2,%3}, [%4];" \
        : "=r"((r)[0]), "=r"((r)[1]), "=r"((r)[2]), "=r"((r)[3]) : "r"(addr))
#define MMA_F16(c, a, b) \
    asm volatile("mma.sync.aligned.m16n8k16.row.col.f32.f16.f16.f32 " \
        "{%0,%1,%2,%3}, {%4,%5,%6,%7}, {%8,%9}, {%0,%1,%2,%3};" \
        : "+f"((c)[0]), "+f"((c)[1]), "+f"((c)[2]), "+f"((c)[3]) \
        : "r"((a)[0]), "r"((a)[1]), "r"((a)[2]), "r"((a)[3]), "r"((b)[0]), "r"((b)[1]))

// ---------------- weight prep: transpose to smem-tile layout, fp16 ----------------
template <int C>
__global__ void prep_kernel(const float* __restrict__ W) {
    uint16_t* dst = (C == 64) ? g_Wt1 : g_Wt2;
    int t = blockIdx.x * blockDim.x + threadIdx.x;
    if (t >= KK * C * COUT) return;
    int d = t & 127;
    int c = (t >> 7) % C;
    int k = t / (C * COUT);
    __half hh = __float2half_rn(W[t]);
    int chunk = c >> 6, cl = c & 63;
    uint16_t* base = dst + (size_t)(k * (C / 64) + chunk) * 9216;
    base[d * 72 + cl] = *(uint16_t*)&hh;
}

// ---------------- profiling landmark (keeps conv1 at launch slot 4) ----------------
__global__ void noop_kernel() {}

// ---------------- gather-GEMM conv via mma.sync fp16 ----------------
// Block: 128 rows x 128 cols, 8 warps (64x32 warp tiles), double-buffered stages,
// 2 CTAs/SM. F16IN: input already fp16 (bn1 applied) -> raw 64ch chunk gather.
static constexpr int SM_IDX   = 0;                   // [KK][128] int = 13824
static constexpr int SM_STAGE = 13824;
static constexpr int BUF_A = 0;                      // 128 rows x 144 B = 18432
static constexpr int BUF_B = 18432;                  // 128 x 144 B = 18432
static constexpr int BUF_STRIDE = 36864;
static constexpr int SM_TOT = SM_STAGE + 2 * BUF_STRIDE;   // 87552

template <int C, bool F16IN>
__global__ void __launch_bounds__(256, 2) conv_mma_kernel(const void* __restrict__ xin_,
                                                          const int*  __restrict__ nbr,
                                                          const uint16_t* __restrict__ Wt,
                                                          float* __restrict__ dst) {
    extern __shared__ char smem[];
    const uint32_t su = smem_to_u32(smem);
    const int tid = threadIdx.x;
    const int wid = tid >> 5, lane = tid & 31;
    const int r0 = blockIdx.x * 128;
    constexpr int CH_PER_K = C / 64;
    constexpr int NCH = KK * CH_PER_K;

    int* s_idx = (int*)(smem + SM_IDX);

    // ---- prologue: neighbor indices ----
    {
        int valid = NROWS - r0; if (valid > 128) valid = 128;
        for (int e = tid; e < 128 * KK; e += 256) {
            int r = e / KK, k = e - r * KK;
            s_idx[k * 128 + r] = (r < valid) ? nbr[(size_t)(r0 + r) * KK + k] : NROWS;
        }
    }
    __syncthreads();

    const int q  = tid & 7;
    const int rb = tid >> 3;         // 0..31

    const int wr = wid & 1, wc = wid >> 1;
    const uint32_t aoff = (uint32_t)((wr * 64 + (lane & 15)) * 144 + (lane >> 4) * 16);
    const uint32_t boff = (uint32_t)((wc * 32 + (lane >> 2)) * 144 + (lane & 3) * 4);

    float acc[4][4][4];
#pragma unroll
    for (int a = 0; a < 4; ++a)
#pragma unroll
        for (int b = 0; b < 4; ++b)
#pragma unroll
            for (int c2 = 0; c2 < 4; ++c2) acc[a][b][c2] = 0.f;

    float4 vf[4];      // fp32 path payload (one 32-ch half)
    uint4  vh[4];      // fp16 path payload (full 64-ch chunk)

    auto stageB = [&](int i, int buf) {
        uint32_t bdst = su + SM_STAGE + buf * BUF_STRIDE + BUF_B;
        const char* bsrc = (const char*)Wt + (size_t)i * 18432;
#pragma unroll
        for (int e = tid; e < 1152; e += 256) cp16(bdst + e * 16, bsrc + e * 16);
    };
    // fp32 input: gather one 32-channel half into registers
    auto loadAf = [&](int i, int half) {
        const int c0 = (i % CH_PER_K) * 64 + half * 32;
        const int* idxk = s_idx + (i / CH_PER_K) * 128;
#pragma unroll
        for (int j = 0; j < 4; ++j) {
            int idx = idxk[rb + j * 32];
            if (idx >= NROWS) vf[j] = make_float4(0.f, 0.f, 0.f, 0.f);
            else vf[j] = *(const float4*)((const float*)xin_ + (size_t)idx * C + c0 + q * 4);
        }
    };
    auto storeAf = [&](int buf, int half) {
        char* aT = smem + SM_STAGE + buf * BUF_STRIDE + BUF_A;
#pragma unroll
        for (int j = 0; j < 4; ++j) {
            uint32_t off = (uint32_t)((rb + j * 32) * 144 + half * 64 + q * 8);
            *(uint2*)(aT + off) = make_uint2(pack_h2(vf[j].x, vf[j].y), pack_h2(vf[j].z, vf[j].w));
        }
    };
    // fp16 input: gather the full 64-channel chunk (raw copy, no conversion)
    auto loadAh = [&](int i) {
        const int c0 = (i % CH_PER_K) * 64;
        const int* idxk = s_idx + (i / CH_PER_K) * 128;
#pragma unroll
        for (int j = 0; j < 4; ++j) {
            int idx = idxk[rb + j * 32];   // sentinel row NROWS is zero-filled in g_h16
            vh[j] = *(const uint4*)((const char*)xin_ + (size_t)idx * (C * 2) + c0 * 2 + q * 16);
        }
    };
    auto storeAh = [&](int buf) {
        char* aT = smem + SM_STAGE + buf * BUF_STRIDE + BUF_A;
#pragma unroll
        for (int j = 0; j < 4; ++j) {
            uint32_t off = (uint32_t)((rb + j * 32) * 144 + q * 16);
            *(uint4*)(aT + off) = vh[j];
        }
    };
    auto mmaHalf = [&](int buf, int h) {
        uint32_t base = su + SM_STAGE + buf * BUF_STRIDE;
        const char* bbase = smem + SM_STAGE + buf * BUF_STRIDE + BUF_B;
#pragma unroll
        for (int ks = 0; ks < 2; ++ks) {
            const uint32_t kb = (uint32_t)((h * 2 + ks) * 32);
            uint32_t a[4][4], b[4][2];
#pragma unroll
            for (int mt = 0; mt < 4; ++mt) LDMX4(a[mt], base + BUF_A + aoff + mt * 2304 + kb);
#pragma unroll
            for (int nt = 0; nt < 4; ++nt) {
                const char* o = bbase + boff + nt * 1152 + kb;
                b[nt][0] = *(const uint32_t*)o;
                b[nt][1] = *(const uint32_t*)(o + 16);
            }
#pragma unroll
            for (int mt = 0; mt < 4; ++mt)
#pragma unroll
                for (int nt = 0; nt < 4; ++nt) MMA_F16(acc[mt][nt], a[mt], b[nt]);
        }
    };

    // ---- pipeline ----
    if (F16IN) {
        stageB(0, 0); CP_COMMIT();
        loadAh(0); storeAh(0);
        CP_WAIT0();
        __syncthreads();
        for (int i = 0; i < NCH; ++i) {
            const int buf = i & 1;
            const bool more = (i + 1 < NCH);
            if (more) { stageB(i + 1, buf ^ 1); CP_COMMIT(); loadAh(i + 1); }
            mmaHalf(buf, 0);
            if (more) storeAh(buf ^ 1);
            mmaHalf(buf, 1);
            if (more) CP_WAIT0();
            __syncthreads();
        }
    } else {
        stageB(0, 0); CP_COMMIT();
        loadAf(0, 0); storeAf(0, 0);
        loadAf(0, 1); storeAf(0, 1);
        CP_WAIT0();
        __syncthreads();
        for (int i = 0; i < NCH; ++i) {
            const int buf = i & 1;
            const bool more = (i + 1 < NCH);
            if (more) { stageB(i + 1, buf ^ 1); CP_COMMIT(); loadAf(i + 1, 0); }
            mmaHalf(buf, 0);
            if (more) { storeAf(buf ^ 1, 0); loadAf(i + 1, 1); }
            mmaHalf(buf, 1);
            if (more) { storeAf(buf ^ 1, 1); CP_WAIT0(); }
            __syncthreads();
        }
    }

    // ---- epilogue: write conv output ----
#pragma unroll
    for (int mt = 0; mt < 4; ++mt) {
        int row = r0 + wr * 64 + mt * 16 + (lane >> 2);
        int col = wc * 32 + (lane & 3) * 2;
#pragma unroll
        for (int nt = 0; nt < 4; ++nt) {
            if (row < NROWS)
                *(float2*)&dst[(size_t)row * COUT + col + nt * 8] =
                    make_float2(acc[mt][nt][0], acc[mt][nt][1]);
            if (row + 8 < NROWS)
                *(float2*)&dst[(size_t)(row + 8) * COUT + col + nt * 8] =
                    make_float2(acc[mt][nt][2], acc[mt][nt][3]);
        }
    }

    // ---- fused BN statistics (per-CTA partials; sentinel rows contribute exact zeros) ----
    {
        float* ssum = (float*)(smem + SM_STAGE);          // [2][128]
        float* ssq  = ssum + 256;                         // [2][128]
        float s[4][2], qq[4][2];
#pragma unroll
        for (int nt = 0; nt < 4; ++nt)
#pragma unroll
            for (int p = 0; p < 2; ++p) {
                float ss = 0.f, sq = 0.f;
#pragma unroll
                for (int mt = 0; mt < 4; ++mt) {
                    float a0 = acc[mt][nt][p], a1 = acc[mt][nt][p + 2];
                    ss += a0 + a1;
                    sq += a0 * a0 + a1 * a1;
                }
#pragma unroll
                for (int o = 4; o <= 16; o <<= 1) {
                    ss += __shfl_xor_sync(0xffffffffu, ss, o);
                    sq += __shfl_xor_sync(0xffffffffu, sq, o);
                }
                s[nt][p] = ss; qq[nt][p] = sq;
            }
        __syncthreads();
        if (lane < 4) {
#pragma unroll
            for (int nt = 0; nt < 4; ++nt)
#pragma unroll
                for (int p = 0; p < 2; ++p) {
                    int col = wc * 32 + lane * 2 + nt * 8 + p;
                    ssum[wr * 128 + col] = s[nt][p];
                    ssq [wr * 128 + col] = qq[nt][p];
                }
        }
        __syncthreads();
        if (tid < 128) {
            float S = ssum[tid] + ssum[128 + tid];
            float Q = ssq [tid] + ssq [128 + tid];
            g_psum[blockIdx.x * COUT + tid] = S;
            g_psq [blockIdx.x * COUT + tid] = Q;
        }
    }
}

// ---------------- stats reduction (deterministic two-stage) ----------------
__global__ void stats_mid_kernel() {
    int c = threadIdx.x;                 // 128
    int b0 = blockIdx.x;                 // 16
    float s = 0.f, q = 0.f;
    for (int b = b0; b < NBLK; b += 16) {
        s += g_psum[b * COUT + c];
        q += g_psq [b * COUT + c];
    }
    g_msum[b0 * COUT + c] = s;
    g_msq [b0 * COUT + c] = q;
}

__global__ void stats_final_kernel(int layer, const float* __restrict__ gamma,
                                   const float* __restrict__ beta) {
    int c = threadIdx.x;  // 128
    float s = 0.f, q = 0.f;
#pragma unroll
    for (int b = 0; b < 16; ++b) {
        s += g_msum[b * COUT + c];
        q += g_msq [b * COUT + c];
    }
    float mu  = s / (float)NROWS;
    float var = q / (float)NROWS - mu * mu;
    float inv = rsqrtf(var + 1e-5f);
    float A = inv * gamma[c];
    g_bnA[layer][c] = A;
    g_bnB[layer][c] = beta[c] - mu * A;
}

// ---------------- h16 = fp16(relu(bn1(y))); zero sentinel row at NROWS ----------------
__global__ void bn_apply16_kernel() {
    size_t total = (size_t)(NROWS + 1) * (COUT / 8);
    for (size_t i = (size_t)blockIdx.x * blockDim.x + threadIdx.x; i < total;
         i += (size_t)gridDim.x * blockDim.x) {
        size_t row = i >> 4;                  // COUT/8 == 16
        int cb = (int)(i & 15) * 8;
        uint4 o = make_uint4(0u, 0u, 0u, 0u);
        if (row < NROWS) {
            float4 v0 = *(const float4*)&g_y[row * COUT + cb];
            float4 v1 = *(const float4*)&g_y[row * COUT + cb + 4];
            float4 A0 = *(const float4*)&g_bnA[0][cb];
            float4 A1 = *(const float4*)&g_bnA[0][cb + 4];
            float4 B0 = *(const float4*)&g_bnB[0][cb];
            float4 B1 = *(const float4*)&g_bnB[0][cb + 4];
            o.x = pack_h2(fmaxf(fmaf(v0.x, A0.x, B0.x), 0.f), fmaxf(fmaf(v0.y, A0.y, B0.y), 0.f));
            o.y = pack_h2(fmaxf(fmaf(v0.z, A0.z, B0.z), 0.f), fmaxf(fmaf(v0.w, A0.w, B0.w), 0.f));
            o.z = pack_h2(fmaxf(fmaf(v1.x, A1.x, B1.x), 0.f), fmaxf(fmaf(v1.y, A1.y, B1.y), 0.f));
            o.w = pack_h2(fmaxf(fmaf(v1.z, A1.z, B1.z), 0.f), fmaxf(fmaf(v1.w, A1.w, B1.w), 0.f));
        }
        *(uint4*)&g_h16[row * COUT + cb] = o;
    }
}

// ---------------- final: out = relu(bn2(y2)) + x @ W_skip ----------------
__global__ void __launch_bounds__(256) final_kernel(const float* __restrict__ x,
                                                    const float* __restrict__ Wskip,
                                                    float* __restrict__ out) {
    __shared__ float sW[CIN * COUT];
    __shared__ float sx[32 * CIN];
    const int tid = threadIdx.x;
    const int r0 = blockIdx.x * 32;

    {
        const float4* W4 = (const float4*)Wskip;
        float4* sW4 = (float4*)sW;
        for (int e = tid; e < CIN * COUT / 4; e += 256) sW4[e] = W4[e];
        float4* sx4 = (float4*)sx;
        for (int e = tid; e < 32 * CIN / 4; e += 256) {
            int r = e >> 4, c4 = (e & 15) * 4;
            int row = r0 + r;
            sx4[e] = (row < NROWS) ? *(const float4*)(x + (size_t)row * CIN + c4)
                                   : make_float4(0.f, 0.f, 0.f, 0.f);
        }
    }
    __syncthreads();

    const int c = tid & 127, rh = tid >> 7;
    float id[16];
#pragma unroll
    for (int i = 0; i < 16; ++i) id[i] = 0.f;

#pragma unroll
    for (int kc = 0; kc < CIN / 8; ++kc) {
        float w[8];
#pragma unroll
        for (int i = 0; i < 8; ++i) w[i] = sW[(kc * 8 + i) * COUT + c];
#pragma unroll
        for (int rr = 0; rr < 16; ++rr) {
            int rl = rh * 16 + rr;
            float4 xa = *(const float4*)&sx[rl * CIN + kc * 8];
            float4 xb = *(const float4*)&sx[rl * CIN + kc * 8 + 4];
            float t = id[rr];
            t = fmaf(xa.x, w[0], t); t = fmaf(xa.y, w[1], t);
            t = fmaf(xa.z, w[2], t); t = fmaf(xa.w, w[3], t);
            t = fmaf(xb.x, w[4], t); t = fmaf(xb.y, w[5], t);
            t = fmaf(xb.z, w[6], t); t = fmaf(xb.w, w[7], t);
            id[rr] = t;
        }
    }

    const float A = g_bnA[1][c], B = g_bnB[1][c];
#pragma unroll
    for (int rr = 0; rr < 16; ++rr) {
        int row = r0 + rh * 16 + rr;
        if (row >= NROWS) continue;
        float v = g_h[(size_t)row * COUT + c];
        out[(size_t)row * COUT + c] = fmaxf(fmaf(v, A, B), 0.f) + id[rr];
    }
}

// ---------------- launch ----------------
extern "C" void kernel_launch(void* const* d_in, const int* in_sizes, int n_in,
                              void* d_out, int out_size) {
    const float* x      = (const float*)d_in[0];
    const int*   nbr    = (const int*)  d_in[1];
    const float* W1     = (const float*)d_in[2];
    const float* gamma1 = (const float*)d_in[3];
    const float* beta1  = (const float*)d_in[4];
    const float* W2     = (const float*)d_in[5];
    const float* gamma2 = (const float*)d_in[6];
    const float* beta2  = (const float*)d_in[7];
    const float* Wskip  = (const float*)d_in[8];
    float* out = (float*)d_out;

    cudaFuncSetAttribute(conv_mma_kernel<64,  false>, cudaFuncAttributeMaxDynamicSharedMemorySize, SM_TOT);
    cudaFuncSetAttribute(conv_mma_kernel<128, true >, cudaFuncAttributeMaxDynamicSharedMemorySize, SM_TOT);

    uint16_t* wt1; cudaGetSymbolAddress((void**)&wt1, g_Wt1);
    uint16_t* wt2; cudaGetSymbolAddress((void**)&wt2, g_Wt2);
    float* y;   cudaGetSymbolAddress((void**)&y,   g_y);
    float* h;   cudaGetSymbolAddress((void**)&h,   g_h);
    void*  h16; cudaGetSymbolAddress(&h16, g_h16);

    prep_kernel<64> <<<(KK * 64  * COUT + 255) / 256, 256>>>(W1);      // launch 1
    prep_kernel<128><<<(KK * 128 * COUT + 255) / 256, 256>>>(W2);      // launch 2
    noop_kernel<<<1, 32>>>();                                          // launch 3 (landmark)

    conv_mma_kernel<64, false><<<NBLK, 256, SM_TOT>>>(x, nbr, wt1, y); // launch 4
    stats_mid_kernel<<<16, 128>>>();
    stats_final_kernel<<<1, 128>>>(0, gamma1, beta1);
    bn_apply16_kernel<<<1024, 256>>>();

    conv_mma_kernel<128, true><<<NBLK, 256, SM_TOT>>>(h16, nbr, wt2, h);
    stats_mid_kernel<<<16, 128>>>();
    stats_final_kernel<<<1, 128>>>(1, gamma2, beta2);

    final_kernel<<<(NROWS + 31) / 32, 256>>>(x, Wskip, out);
}

// round 13
// speedup vs baseline: 11.0773x; 1.0277x over previous
#include <cuda_runtime.h>
#include <cuda_fp16.h>
#include <cstdint>

#define NROWS 100000
#define KK    27
#define CIN   64
#define COUT  128
#define NBLK  782            // (NROWS+127)/128
#define NPART 64             // stats mid-reduction width

// ---------------- scratch (static device globals; no cudaMalloc) ----------------
__device__ float g_y[(size_t)NROWS * COUT];              // conv1 output (fp32)
__device__ float g_h[(size_t)NROWS * COUT];              // conv2 output (fp32)
__device__ __align__(16) __half g_x16[(size_t)(NROWS + 1) * CIN];   // fp16(x), zero sentinel
__device__ __align__(16) __half g_h16[(size_t)(NROWS + 1) * COUT];  // fp16(relu(bn1(y))), zero sentinel
__device__ float g_psum[NBLK * COUT];
__device__ float g_psq [NBLK * COUT];
__device__ float g_msum[NPART * COUT];
__device__ float g_msq [NPART * COUT];
__device__ float g_bnA[2][COUT];
__device__ float g_bnB[2][COUT];
// fp16 weights laid out as the smem B tile: per (k, 64c-chunk): [d=128][72] half (18432 B)
__device__ __align__(16) uint16_t g_Wt1[KK * 1 * 9216];   // conv1: C=64  -> 1 chunk/k
__device__ __align__(16) uint16_t g_Wt2[KK * 2 * 9216];   // conv2: C=128 -> 2 chunks/k

// ---------------- helpers ----------------
__device__ __forceinline__ uint32_t smem_to_u32(const void* p) {
    uint32_t a;
    asm("{ .reg .u64 t; cvta.to.shared.u64 t, %1; cvt.u32.u64 %0, t; }" : "=r"(a) : "l"(p));
    return a;
}
__device__ __forceinline__ uint32_t pack_h2(float a, float b) {
    __half2 t = __floats2half2_rn(a, b);
    return *(uint32_t*)&t;
}
__device__ __forceinline__ void cp16(uint32_t dst, const void* src) {
    asm volatile("cp.async.cg.shared.global [%0], [%1], 16;" :: "r"(dst), "l"(src));
}
#define CP_COMMIT() asm volatile("cp.async.commit_group;" ::: "memory")
#define CP_WAIT0()  asm volatile("cp.async.wait_group 0;"  ::: "memory")
#define LDMX4(r, addr) \
    asm volatile("ldmatrix.sync.aligned.m8n8.x4.shared.b16 {%0,%1,%2,%3}, [%4];" \
        : "=r"((r)[0]), "=r"((r)[1]), "=r"((r)[2]), "=r"((r)[3]) : "r"(addr))
#define MMA_F16(c, a, b) \
    asm volatile("mma.sync.aligned.m16n8k16.row.col.f32.f16.f16.f32 " \
        "{%0,%1,%2,%3}, {%4,%5,%6,%7}, {%8,%9}, {%0,%1,%2,%3};" \
        : "+f"((c)[0]), "+f"((c)[1]), "+f"((c)[2]), "+f"((c)[3]) \
        : "r"((a)[0]), "r"((a)[1]), "r"((a)[2]), "r"((a)[3]), "r"((b)[0]), "r"((b)[1]))

// ---------------- weight prep: transpose to smem-tile layout, fp16 ----------------
template <int C>
__global__ void prep_kernel(const float* __restrict__ W) {
    uint16_t* dst = (C == 64) ? g_Wt1 : g_Wt2;
    int t = blockIdx.x * blockDim.x + threadIdx.x;
    if (t >= KK * C * COUT) return;
    int d = t & 127;
    int c = (t >> 7) % C;
    int k = t / (C * COUT);
    __half hh = __float2half_rn(W[t]);
    int chunk = c >> 6, cl = c & 63;
    uint16_t* base = dst + (size_t)(k * (C / 64) + chunk) * 9216;
    base[d * 72 + cl] = *(uint16_t*)&hh;
}

// ---------------- x -> fp16 (bitwise same rounding conv1 used to do); zero sentinel ----
__global__ void x16_kernel(const float* __restrict__ x) {
    size_t total = (size_t)(NROWS + 1) * (CIN / 8);
    for (size_t i = (size_t)blockIdx.x * blockDim.x + threadIdx.x; i < total;
         i += (size_t)gridDim.x * blockDim.x) {
        size_t row = i >> 3;                  // CIN/8 == 8
        int cb = (int)(i & 7) * 8;
        uint4 o = make_uint4(0u, 0u, 0u, 0u);
        if (row < NROWS) {
            float4 v0 = *(const float4*)&x[row * CIN + cb];
            float4 v1 = *(const float4*)&x[row * CIN + cb + 4];
            o.x = pack_h2(v0.x, v0.y);
            o.y = pack_h2(v0.z, v0.w);
            o.z = pack_h2(v1.x, v1.y);
            o.w = pack_h2(v1.z, v1.w);
        }
        *(uint4*)&g_x16[row * CIN + cb] = o;
    }
}

// ---------------- gather-GEMM conv via mma.sync fp16 (fp16 input, raw gather) ---------
// Block: 128 rows x 128 cols, 8 warps (64x32 warp tiles), double-buffered stages, 2 CTAs/SM.
static constexpr int SM_IDX   = 0;                   // [KK][128] int = 13824
static constexpr int SM_STAGE = 13824;
static constexpr int BUF_A = 0;                      // 128 rows x 144 B = 18432
static constexpr int BUF_B = 18432;                  // 128 x 144 B = 18432
static constexpr int BUF_STRIDE = 36864;
static constexpr int SM_TOT = SM_STAGE + 2 * BUF_STRIDE;   // 87552

template <int C>
__global__ void __launch_bounds__(256, 2) conv_mma_kernel(const __half* __restrict__ xin,
                                                          const int*  __restrict__ nbr,
                                                          const uint16_t* __restrict__ Wt,
                                                          float* __restrict__ dst) {
    extern __shared__ char smem[];
    const uint32_t su = smem_to_u32(smem);
    const int tid = threadIdx.x;
    const int wid = tid >> 5, lane = tid & 31;
    const int r0 = blockIdx.x * 128;
    constexpr int CH_PER_K = C / 64;
    constexpr int NCH = KK * CH_PER_K;

    int* s_idx = (int*)(smem + SM_IDX);

    // ---- prologue: neighbor indices ----
    {
        int valid = NROWS - r0; if (valid > 128) valid = 128;
        for (int e = tid; e < 128 * KK; e += 256) {
            int r = e / KK, k = e - r * KK;
            s_idx[k * 128 + r] = (r < valid) ? nbr[(size_t)(r0 + r) * KK + k] : NROWS;
        }
    }
    __syncthreads();

    const int q  = tid & 7;
    const int rb = tid >> 3;         // 0..31

    const int wr = wid & 1, wc = wid >> 1;
    const uint32_t aoff = (uint32_t)((wr * 64 + (lane & 15)) * 144 + (lane >> 4) * 16);
    const uint32_t boff = (uint32_t)((wc * 32 + (lane >> 2)) * 144 + (lane & 3) * 4);

    float acc[4][4][4];
#pragma unroll
    for (int a = 0; a < 4; ++a)
#pragma unroll
        for (int b = 0; b < 4; ++b)
#pragma unroll
            for (int c2 = 0; c2 < 4; ++c2) acc[a][b][c2] = 0.f;

    uint4 vh[4];   // gathered fp16 payload: 4 rows x 16 B (one 64ch chunk slice)

    auto stageB = [&](int i, int buf) {
        uint32_t bdst = su + SM_STAGE + buf * BUF_STRIDE + BUF_B;
        const char* bsrc = (const char*)Wt + (size_t)i * 18432;
#pragma unroll
        for (int e = tid; e < 1152; e += 256) cp16(bdst + e * 16, bsrc + e * 16);
    };
    auto loadA = [&](int i) {
        const int c0 = (i % CH_PER_K) * 64;
        const int* idxk = s_idx + (i / CH_PER_K) * 128;
#pragma unroll
        for (int j = 0; j < 4; ++j) {
            int idx = idxk[rb + j * 32];   // sentinel row is zero-filled in the fp16 buffer
            vh[j] = *(const uint4*)((const char*)xin + (size_t)idx * (C * 2) + c0 * 2 + q * 16);
        }
    };
    auto storeA = [&](int buf) {
        char* aT = smem + SM_STAGE + buf * BUF_STRIDE + BUF_A;
#pragma unroll
        for (int j = 0; j < 4; ++j) {
            uint32_t off = (uint32_t)((rb + j * 32) * 144 + q * 16);
            *(uint4*)(aT + off) = vh[j];
        }
    };
    auto mmaHalf = [&](int buf, int h) {
        uint32_t base = su + SM_STAGE + buf * BUF_STRIDE;
        const char* bbase = smem + SM_STAGE + buf * BUF_STRIDE + BUF_B;
#pragma unroll
        for (int ks = 0; ks < 2; ++ks) {
            const uint32_t kb = (uint32_t)((h * 2 + ks) * 32);
            uint32_t a[4][4], b[4][2];
#pragma unroll
            for (int mt = 0; mt < 4; ++mt) LDMX4(a[mt], base + BUF_A + aoff + mt * 2304 + kb);
#pragma unroll
            for (int nt = 0; nt < 4; ++nt) {
                const char* o = bbase + boff + nt * 1152 + kb;
                b[nt][0] = *(const uint32_t*)o;
                b[nt][1] = *(const uint32_t*)(o + 16);
            }
#pragma unroll
            for (int mt = 0; mt < 4; ++mt)
#pragma unroll
                for (int nt = 0; nt < 4; ++nt) MMA_F16(acc[mt][nt], a[mt], b[nt]);
        }
    };

    // ---- pipeline ----
    stageB(0, 0); CP_COMMIT();
    loadA(0); storeA(0);
    CP_WAIT0();
    __syncthreads();
    for (int i = 0; i < NCH; ++i) {
        const int buf = i & 1;
        const bool more = (i + 1 < NCH);
        if (more) { stageB(i + 1, buf ^ 1); CP_COMMIT(); loadA(i + 1); }
        mmaHalf(buf, 0);
        if (more) storeA(buf ^ 1);
        mmaHalf(buf, 1);
        if (more) CP_WAIT0();
        __syncthreads();
    }

    // ---- epilogue: write conv output ----
#pragma unroll
    for (int mt = 0; mt < 4; ++mt) {
        int row = r0 + wr * 64 + mt * 16 + (lane >> 2);
        int col = wc * 32 + (lane & 3) * 2;
#pragma unroll
        for (int nt = 0; nt < 4; ++nt) {
            if (row < NROWS)
                *(float2*)&dst[(size_t)row * COUT + col + nt * 8] =
                    make_float2(acc[mt][nt][0], acc[mt][nt][1]);
            if (row + 8 < NROWS)
                *(float2*)&dst[(size_t)(row + 8) * COUT + col + nt * 8] =
                    make_float2(acc[mt][nt][2], acc[mt][nt][3]);
        }
    }

    // ---- fused BN statistics (per-CTA partials; sentinel rows contribute exact zeros) ----
    {
        float* ssum = (float*)(smem + SM_STAGE);          // [2][128]
        float* ssq  = ssum + 256;                         // [2][128]
        float s[4][2], qq[4][2];
#pragma unroll
        for (int nt = 0; nt < 4; ++nt)
#pragma unroll
            for (int p = 0; p < 2; ++p) {
                float ss = 0.f, sq = 0.f;
#pragma unroll
                for (int mt = 0; mt < 4; ++mt) {
                    float a0 = acc[mt][nt][p], a1 = acc[mt][nt][p + 2];
                    ss += a0 + a1;
                    sq += a0 * a0 + a1 * a1;
                }
#pragma unroll
                for (int o = 4; o <= 16; o <<= 1) {
                    ss += __shfl_xor_sync(0xffffffffu, ss, o);
                    sq += __shfl_xor_sync(0xffffffffu, sq, o);
                }
                s[nt][p] = ss; qq[nt][p] = sq;
            }
        __syncthreads();
        if (lane < 4) {
#pragma unroll
            for (int nt = 0; nt < 4; ++nt)
#pragma unroll
                for (int p = 0; p < 2; ++p) {
                    int col = wc * 32 + lane * 2 + nt * 8 + p;
                    ssum[wr * 128 + col] = s[nt][p];
                    ssq [wr * 128 + col] = qq[nt][p];
                }
        }
        __syncthreads();
        if (tid < 128) {
            g_psum[blockIdx.x * COUT + tid] = ssum[tid] + ssum[128 + tid];
            g_psq [blockIdx.x * COUT + tid] = ssq [tid] + ssq [128 + tid];
        }
    }
}

// ---------------- stats reduction (deterministic two-stage) ----------------
__global__ void stats_mid_kernel() {
    int c = threadIdx.x;                 // 128
    int b0 = blockIdx.x;                 // NPART
    float s = 0.f, q = 0.f;
    for (int b = b0; b < NBLK; b += NPART) {
        s += g_psum[b * COUT + c];
        q += g_psq [b * COUT + c];
    }
    g_msum[b0 * COUT + c] = s;
    g_msq [b0 * COUT + c] = q;
}

__global__ void stats_final_kernel(int layer, const float* __restrict__ gamma,
                                   const float* __restrict__ beta) {
    int c = threadIdx.x;  // 128
    float s = 0.f, q = 0.f;
#pragma unroll
    for (int b = 0; b < NPART; ++b) {
        s += g_msum[b * COUT + c];
        q += g_msq [b * COUT + c];
    }
    float mu  = s / (float)NROWS;
    float var = q / (float)NROWS - mu * mu;
    float inv = rsqrtf(var + 1e-5f);
    float A = inv * gamma[c];
    g_bnA[layer][c] = A;
    g_bnB[layer][c] = beta[c] - mu * A;
}

// ---------------- h16 = fp16(relu(bn1(y))); zero sentinel row at NROWS ----------------
__global__ void bn_apply16_kernel() {
    size_t total = (size_t)(NROWS + 1) * (COUT / 8);
    for (size_t i = (size_t)blockIdx.x * blockDim.x + threadIdx.x; i < total;
         i += (size_t)gridDim.x * blockDim.x) {
        size_t row = i >> 4;                  // COUT/8 == 16
        int cb = (int)(i & 15) * 8;
        uint4 o = make_uint4(0u, 0u, 0u, 0u);
        if (row < NROWS) {
            float4 v0 = *(const float4*)&g_y[row * COUT + cb];
            float4 v1 = *(const float4*)&g_y[row * COUT + cb + 4];
            float4 A0 = *(const float4*)&g_bnA[0][cb];
            float4 A1 = *(const float4*)&g_bnA[0][cb + 4];
            float4 B0 = *(const float4*)&g_bnB[0][cb];
            float4 B1 = *(const float4*)&g_bnB[0][cb + 4];
            o.x = pack_h2(fmaxf(fmaf(v0.x, A0.x, B0.x), 0.f), fmaxf(fmaf(v0.y, A0.y, B0.y), 0.f));
            o.y = pack_h2(fmaxf(fmaf(v0.z, A0.z, B0.z), 0.f), fmaxf(fmaf(v0.w, A0.w, B0.w), 0.f));
            o.z = pack_h2(fmaxf(fmaf(v1.x, A1.x, B1.x), 0.f), fmaxf(fmaf(v1.y, A1.y, B1.y), 0.f));
            o.w = pack_h2(fmaxf(fmaf(v1.z, A1.z, B1.z), 0.f), fmaxf(fmaf(v1.w, A1.w, B1.w), 0.f));
        }
        *(uint4*)&g_h16[row * COUT + cb] = o;
    }
}

// ---------------- final: out = relu(bn2(y2)) + x @ W_skip ----------------
__global__ void __launch_bounds__(256) final_kernel(const float* __restrict__ x,
                                                    const float* __restrict__ Wskip,
                                                    float* __restrict__ out) {
    __shared__ float sW[CIN * COUT];
    __shared__ float sx[32 * CIN];
    const int tid = threadIdx.x;
    const int r0 = blockIdx.x * 32;

    {
        const float4* W4 = (const float4*)Wskip;
        float4* sW4 = (float4*)sW;
        for (int e = tid; e < CIN * COUT / 4; e += 256) sW4[e] = W4[e];
        float4* sx4 = (float4*)sx;
        for (int e = tid; e < 32 * CIN / 4; e += 256) {
            int r = e >> 4, c4 = (e & 15) * 4;
            int row = r0 + r;
            sx4[e] = (row < NROWS) ? *(const float4*)(x + (size_t)row * CIN + c4)
                                   : make_float4(0.f, 0.f, 0.f, 0.f);
        }
    }
    __syncthreads();

    const int c = tid & 127, rh = tid >> 7;
    float id[16];
#pragma unroll
    for (int i = 0; i < 16; ++i) id[i] = 0.f;

#pragma unroll
    for (int kc = 0; kc < CIN / 8; ++kc) {
        float w[8];
#pragma unroll
        for (int i = 0; i < 8; ++i) w[i] = sW[(kc * 8 + i) * COUT + c];
#pragma unroll
        for (int rr = 0; rr < 16; ++rr) {
            int rl = rh * 16 + rr;
            float4 xa = *(const float4*)&sx[rl * CIN + kc * 8];
            float4 xb = *(const float4*)&sx[rl * CIN + kc * 8 + 4];
            float t = id[rr];
            t = fmaf(xa.x, w[0], t); t = fmaf(xa.y, w[1], t);
            t = fmaf(xa.z, w[2], t); t = fmaf(xa.w, w[3], t);
            t = fmaf(xb.x, w[4], t); t = fmaf(xb.y, w[5], t);
            t = fmaf(xb.z, w[6], t); t = fmaf(xb.w, w[7], t);
            id[rr] = t;
        }
    }

    const float A = g_bnA[1][c], B = g_bnB[1][c];
#pragma unroll
    for (int rr = 0; rr < 16; ++rr) {
        int row = r0 + rh * 16 + rr;
        if (row >= NROWS) continue;
        float v = g_h[(size_t)row * COUT + c];
        out[(size_t)row * COUT + c] = fmaxf(fmaf(v, A, B), 0.f) + id[rr];
    }
}

// ---------------- launch ----------------
extern "C" void kernel_launch(void* const* d_in, const int* in_sizes, int n_in,
                              void* d_out, int out_size) {
    const float* x      = (const float*)d_in[0];
    const int*   nbr    = (const int*)  d_in[1];
    const float* W1     = (const float*)d_in[2];
    const float* gamma1 = (const float*)d_in[3];
    const float* beta1  = (const float*)d_in[4];
    const float* W2     = (const float*)d_in[5];
    const float* gamma2 = (const float*)d_in[6];
    const float* beta2  = (const float*)d_in[7];
    const float* Wskip  = (const float*)d_in[8];
    float* out = (float*)d_out;

    cudaFuncSetAttribute(conv_mma_kernel<64>,  cudaFuncAttributeMaxDynamicSharedMemorySize, SM_TOT);
    cudaFuncSetAttribute(conv_mma_kernel<128>, cudaFuncAttributeMaxDynamicSharedMemorySize, SM_TOT);

    uint16_t* wt1; cudaGetSymbolAddress((void**)&wt1, g_Wt1);
    uint16_t* wt2; cudaGetSymbolAddress((void**)&wt2, g_Wt2);
    float* y;   cudaGetSymbolAddress((void**)&y,   g_y);
    float* h;   cudaGetSymbolAddress((void**)&h,   g_h);
    void*  x16; cudaGetSymbolAddress(&x16, g_x16);
    void*  h16; cudaGetSymbolAddress(&h16, g_h16);

    prep_kernel<64> <<<(KK * 64  * COUT + 255) / 256, 256>>>(W1);         // launch 1
    prep_kernel<128><<<(KK * 128 * COUT + 255) / 256, 256>>>(W2);         // launch 2
    x16_kernel<<<512, 256>>>(x);                                          // launch 3

    conv_mma_kernel<64><<<NBLK, 256, SM_TOT>>>((const __half*)x16, nbr, wt1, y);  // launch 4
    stats_mid_kernel<<<NPART, 128>>>();
    stats_final_kernel<<<1, 128>>>(0, gamma1, beta1);
    bn_apply16_kernel<<<1024, 256>>>();

    conv_mma_kernel<128><<<NBLK, 256, SM_TOT>>>((const __half*)h16, nbr, wt2, h);
    stats_mid_kernel<<<NPART, 128>>>();
    stats_final_kernel<<<1, 128>>>(1, gamma2, beta2);

    final_kernel<<<(NROWS + 31) / 32, 256>>>(x, Wskip, out);
}

// round 16
// speedup vs baseline: 11.4039x; 1.0295x over previous
#include <cuda_runtime.h>
#include <cuda_fp16.h>
#include <cstdint>

#define NROWS 100000
#define KK    27
#define CIN   64
#define COUT  128
#define NBLK  782            // (NROWS+127)/128
#define NPART 64             // stats mid-reduction width

// ---------------- scratch (static device globals; no cudaMalloc) ----------------
__device__ float g_y[(size_t)NROWS * COUT];              // conv1 output (fp32)
__device__ float g_h[(size_t)NROWS * COUT];              // conv2 output (fp32)
__device__ __align__(16) __half g_x16[(size_t)(NROWS + 1) * CIN];   // fp16(x), zero sentinel
__device__ __align__(16) __half g_h16[(size_t)(NROWS + 1) * COUT];  // fp16(relu(bn1(y))), zero sentinel
__device__ float g_psum[NBLK * COUT];
__device__ float g_psq [NBLK * COUT];
__device__ float g_msum[NPART * COUT];
__device__ float g_msq [NPART * COUT];
__device__ float g_bnA[2][COUT];
__device__ float g_bnB[2][COUT];
// fp16 weights laid out as the smem B tile: per (k, 64c-chunk): [d=128][72] half (18432 B)
__device__ __align__(16) uint16_t g_Wt1[KK * 1 * 9216];   // conv1: C=64  -> 1 chunk/k
__device__ __align__(16) uint16_t g_Wt2[KK * 2 * 9216];   // conv2: C=128 -> 2 chunks/k

// ---------------- helpers ----------------
__device__ __forceinline__ uint32_t smem_to_u32(const void* p) {
    uint32_t a;
    asm("{ .reg .u64 t; cvta.to.shared.u64 t, %1; cvt.u32.u64 %0, t; }" : "=r"(a) : "l"(p));
    return a;
}
__device__ __forceinline__ uint32_t pack_h2(float a, float b) {
    __half2 t = __floats2half2_rn(a, b);
    return *(uint32_t*)&t;
}
__device__ __forceinline__ void cp16(uint32_t dst, const void* src) {
    asm volatile("cp.async.cg.shared.global [%0], [%1], 16;" :: "r"(dst), "l"(src));
}
#define CP_COMMIT() asm volatile("cp.async.commit_group;" ::: "memory")
#define CP_WAIT0()  asm volatile("cp.async.wait_group 0;"  ::: "memory")
#define LDMX4(r, addr) \
    asm volatile("ldmatrix.sync.aligned.m8n8.x4.shared.b16 {%0,%1,%2,%3}, [%4];" \
        : "=r"((r)[0]), "=r"((r)[1]), "=r"((r)[2]), "=r"((r)[3]) : "r"(addr))
#define MMA_F16(c, a, b) \
    asm volatile("mma.sync.aligned.m16n8k16.row.col.f32.f16.f16.f32 " \
        "{%0,%1,%2,%3}, {%4,%5,%6,%7}, {%8,%9}, {%0,%1,%2,%3};" \
        : "+f"((c)[0]), "+f"((c)[1]), "+f"((c)[2]), "+f"((c)[3]) \
        : "r"((a)[0]), "r"((a)[1]), "r"((a)[2]), "r"((a)[3]), "r"((b)[0]), "r"((b)[1]))

// ---------------- weight prep: transpose to smem-tile layout, fp16 ----------------
template <int C>
__global__ void prep_kernel(const float* __restrict__ W) {
    uint16_t* dst = (C == 64) ? g_Wt1 : g_Wt2;
    int t = blockIdx.x * blockDim.x + threadIdx.x;
    if (t >= KK * C * COUT) return;
    int d = t & 127;
    int c = (t >> 7) % C;
    int k = t / (C * COUT);
    __half hh = __float2half_rn(W[t]);
    int chunk = c >> 6, cl = c & 63;
    uint16_t* base = dst + (size_t)(k * (C / 64) + chunk) * 9216;
    base[d * 72 + cl] = *(uint16_t*)&hh;
}

// ---------------- x -> fp16 (bitwise same rounding conv1 used to do); zero sentinel ----
__global__ void x16_kernel(const float* __restrict__ x) {
    size_t total = (size_t)(NROWS + 1) * (CIN / 8);
    for (size_t i = (size_t)blockIdx.x * blockDim.x + threadIdx.x; i < total;
         i += (size_t)gridDim.x * blockDim.x) {
        size_t row = i >> 3;                  // CIN/8 == 8
        int cb = (int)(i & 7) * 8;
        uint4 o = make_uint4(0u, 0u, 0u, 0u);
        if (row < NROWS) {
            float4 v0 = *(const float4*)&x[row * CIN + cb];
            float4 v1 = *(const float4*)&x[row * CIN + cb + 4];
            o.x = pack_h2(v0.x, v0.y);
            o.y = pack_h2(v0.z, v0.w);
            o.z = pack_h2(v1.x, v1.y);
            o.w = pack_h2(v1.z, v1.w);
        }
        *(uint4*)&g_x16[row * CIN + cb] = o;
    }
}

// ---------------- gather-GEMM conv via mma.sync fp16 (fp16 input, raw gather) ---------
// Block: 128 rows x 128 cols, 8 warps (64x32 warp tiles), double-buffered stages, 2 CTAs/SM.
// B fragments loaded via ldmatrix.x4 (2 nt tiles per op).
static constexpr int SM_IDX   = 0;                   // [KK][128] int = 13824
static constexpr int SM_STAGE = 13824;
static constexpr int BUF_A = 0;                      // 128 rows x 144 B = 18432
static constexpr int BUF_B = 18432;                  // 128 x 144 B = 18432
static constexpr int BUF_STRIDE = 36864;
static constexpr int SM_TOT = SM_STAGE + 2 * BUF_STRIDE;   // 87552

template <int C>
__global__ void __launch_bounds__(256, 2) conv_mma_kernel(const __half* __restrict__ xin,
                                                          const int*  __restrict__ nbr,
                                                          const uint16_t* __restrict__ Wt,
                                                          float* __restrict__ dst) {
    extern __shared__ char smem[];
    const uint32_t su = smem_to_u32(smem);
    const int tid = threadIdx.x;
    const int wid = tid >> 5, lane = tid & 31;
    const int r0 = blockIdx.x * 128;
    constexpr int CH_PER_K = C / 64;
    constexpr int NCH = KK * CH_PER_K;

    int* s_idx = (int*)(smem + SM_IDX);

    // ---- prologue: neighbor indices ----
    {
        int valid = NROWS - r0; if (valid > 128) valid = 128;
        for (int e = tid; e < 128 * KK; e += 256) {
            int r = e / KK, k = e - r * KK;
            s_idx[k * 128 + r] = (r < valid) ? nbr[(size_t)(r0 + r) * KK + k] : NROWS;
        }
    }
    __syncthreads();

    const int q  = tid & 7;
    const int rb = tid >> 3;         // 0..31

    const int wr = wid & 1, wc = wid >> 1;
    const uint32_t aoff = (uint32_t)((wr * 64 + (lane & 15)) * 144 + (lane >> 4) * 16);
    // B ldmatrix lane address: row = wc*32 + (lane>>4)*8 + (lane&7), khalf = (lane>>3)&1
    const uint32_t boffm = (uint32_t)((wc * 32 + (lane >> 4) * 8 + (lane & 7)) * 144 +
                                      ((lane >> 3) & 1) * 16);

    float acc[4][4][4];
#pragma unroll
    for (int a = 0; a < 4; ++a)
#pragma unroll
        for (int b = 0; b < 4; ++b)
#pragma unroll
            for (int c2 = 0; c2 < 4; ++c2) acc[a][b][c2] = 0.f;

    uint4 vh[4];   // gathered fp16 payload: 4 rows x 16 B (one 64ch chunk slice)

    auto stageB = [&](int i, int buf) {
        uint32_t bdst = su + SM_STAGE + buf * BUF_STRIDE + BUF_B;
        const char* bsrc = (const char*)Wt + (size_t)i * 18432;
#pragma unroll
        for (int e = tid; e < 1152; e += 256) cp16(bdst + e * 16, bsrc + e * 16);
    };
    auto loadA = [&](int i) {
        const int c0 = (i % CH_PER_K) * 64;
        const int* idxk = s_idx + (i / CH_PER_K) * 128;
#pragma unroll
        for (int j = 0; j < 4; ++j) {
            int idx = idxk[rb + j * 32];   // sentinel row is zero-filled in the fp16 buffer
            vh[j] = *(const uint4*)((const char*)xin + (size_t)idx * (C * 2) + c0 * 2 + q * 16);
        }
    };
    auto storeA = [&](int buf) {
        char* aT = smem + SM_STAGE + buf * BUF_STRIDE + BUF_A;
#pragma unroll
        for (int j = 0; j < 4; ++j) {
            uint32_t off = (uint32_t)((rb + j * 32) * 144 + q * 16);
            *(uint4*)(aT + off) = vh[j];
        }
    };
    auto mmaHalf = [&](int buf, int h) {
        uint32_t base = su + SM_STAGE + buf * BUF_STRIDE;
#pragma unroll
        for (int ks = 0; ks < 2; ++ks) {
            const uint32_t kb = (uint32_t)((h * 2 + ks) * 32);
            uint32_t a[4][4], b[4][2];
#pragma unroll
            for (int mt = 0; mt < 4; ++mt) LDMX4(a[mt], base + BUF_A + aoff + mt * 2304 + kb);
#pragma unroll
            for (int ntp = 0; ntp < 2; ++ntp) {
                uint32_t bb[4];
                LDMX4(bb, base + BUF_B + boffm + ntp * 2304 + kb);
                b[2 * ntp][0]     = bb[0];
                b[2 * ntp][1]     = bb[1];
                b[2 * ntp + 1][0] = bb[2];
                b[2 * ntp + 1][1] = bb[3];
            }
#pragma unroll
            for (int mt = 0; mt < 4; ++mt)
#pragma unroll
                for (int nt = 0; nt < 4; ++nt) MMA_F16(acc[mt][nt], a[mt], b[nt]);
        }
    };

    // ---- pipeline ----
    stageB(0, 0); CP_COMMIT();
    loadA(0); storeA(0);
    CP_WAIT0();
    __syncthreads();
    for (int i = 0; i < NCH; ++i) {
        const int buf = i & 1;
        const bool more = (i + 1 < NCH);
        if (more) { stageB(i + 1, buf ^ 1); CP_COMMIT(); loadA(i + 1); }
        mmaHalf(buf, 0);
        if (more) storeA(buf ^ 1);
        mmaHalf(buf, 1);
        if (more) CP_WAIT0();
        __syncthreads();
    }

    // ---- epilogue: write conv output ----
#pragma unroll
    for (int mt = 0; mt < 4; ++mt) {
        int row = r0 + wr * 64 + mt * 16 + (lane >> 2);
        int col = wc * 32 + (lane & 3) * 2;
#pragma unroll
        for (int nt = 0; nt < 4; ++nt) {
            if (row < NROWS)
                *(float2*)&dst[(size_t)row * COUT + col + nt * 8] =
                    make_float2(acc[mt][nt][0], acc[mt][nt][1]);
            if (row + 8 < NROWS)
                *(float2*)&dst[(size_t)(row + 8) * COUT + col + nt * 8] =
                    make_float2(acc[mt][nt][2], acc[mt][nt][3]);
        }
    }

    // ---- fused BN statistics (per-CTA partials; sentinel rows contribute exact zeros) ----
    {
        float* ssum = (float*)(smem + SM_STAGE);          // [2][128]
        float* ssq  = ssum + 256;                         // [2][128]
        float s[4][2], qq[4][2];
#pragma unroll
        for (int nt = 0; nt < 4; ++nt)
#pragma unroll
            for (int p = 0; p < 2; ++p) {
                float ss = 0.f, sq = 0.f;
#pragma unroll
                for (int mt = 0; mt < 4; ++mt) {
                    float a0 = acc[mt][nt][p], a1 = acc[mt][nt][p + 2];
                    ss += a0 + a1;
                    sq += a0 * a0 + a1 * a1;
                }
#pragma unroll
                for (int o = 4; o <= 16; o <<= 1) {
                    ss += __shfl_xor_sync(0xffffffffu, ss, o);
                    sq += __shfl_xor_sync(0xffffffffu, sq, o);
                }
                s[nt][p] = ss; qq[nt][p] = sq;
            }
        __syncthreads();
        if (lane < 4) {
#pragma unroll
            for (int nt = 0; nt < 4; ++nt)
#pragma unroll
                for (int p = 0; p < 2; ++p) {
                    int col = wc * 32 + lane * 2 + nt * 8 + p;
                    ssum[wr * 128 + col] = s[nt][p];
                    ssq [wr * 128 + col] = qq[nt][p];
                }
        }
        __syncthreads();
        if (tid < 128) {
            g_psum[blockIdx.x * COUT + tid] = ssum[tid] + ssum[128 + tid];
            g_psq [blockIdx.x * COUT + tid] = ssq [tid] + ssq [128 + tid];
        }
    }
}

// ---------------- stats reduction (deterministic two-stage) ----------------
__global__ void stats_mid_kernel() {
    int c = threadIdx.x;                 // 128
    int b0 = blockIdx.x;                 // NPART
    float s = 0.f, q = 0.f;
    for (int b = b0; b < NBLK; b += NPART) {
        s += g_psum[b * COUT + c];
        q += g_psq [b * COUT + c];
    }
    g_msum[b0 * COUT + c] = s;
    g_msq [b0 * COUT + c] = q;
}

__global__ void stats_final_kernel(int layer, const float* __restrict__ gamma,
                                   const float* __restrict__ beta) {
    int c = threadIdx.x;  // 128
    float s = 0.f, q = 0.f;
#pragma unroll
    for (int b = 0; b < NPART; ++b) {
        s += g_msum[b * COUT + c];
        q += g_msq [b * COUT + c];
    }
    float mu  = s / (float)NROWS;
    float var = q / (float)NROWS - mu * mu;
    float inv = rsqrtf(var + 1e-5f);
    float A = inv * gamma[c];
    g_bnA[layer][c] = A;
    g_bnB[layer][c] = beta[c] - mu * A;
}

// ---------------- h16 = fp16(relu(bn1(y))); zero sentinel row at NROWS ----------------
__global__ void bn_apply16_kernel() {
    size_t total = (size_t)(NROWS + 1) * (COUT / 8);
    for (size_t i = (size_t)blockIdx.x * blockDim.x + threadIdx.x; i < total;
         i += (size_t)gridDim.x * blockDim.x) {
        size_t row = i >> 4;                  // COUT/8 == 16
        int cb = (int)(i & 15) * 8;
        uint4 o = make_uint4(0u, 0u, 0u, 0u);
        if (row < NROWS) {
            float4 v0 = *(const float4*)&g_y[row * COUT + cb];
            float4 v1 = *(const float4*)&g_y[row * COUT + cb + 4];
            float4 A0 = *(const float4*)&g_bnA[0][cb];
            float4 A1 = *(const float4*)&g_bnA[0][cb + 4];
            float4 B0 = *(const float4*)&g_bnB[0][cb];
            float4 B1 = *(const float4*)&g_bnB[0][cb + 4];
            o.x = pack_h2(fmaxf(fmaf(v0.x, A0.x, B0.x), 0.f), fmaxf(fmaf(v0.y, A0.y, B0.y), 0.f));
            o.y = pack_h2(fmaxf(fmaf(v0.z, A0.z, B0.z), 0.f), fmaxf(fmaf(v0.w, A0.w, B0.w), 0.f));
            o.z = pack_h2(fmaxf(fmaf(v1.x, A1.x, B1.x), 0.f), fmaxf(fmaf(v1.y, A1.y, B1.y), 0.f));
            o.w = pack_h2(fmaxf(fmaf(v1.z, A1.z, B1.z), 0.f), fmaxf(fmaf(v1.w, A1.w, B1.w), 0.f));
        }
        *(uint4*)&g_h16[row * COUT + cb] = o;
    }
}

// ---------------- final: out = relu(bn2(y2)) + x @ W_skip ----------------
__global__ void __launch_bounds__(256) final_kernel(const float* __restrict__ x,
                                                    const float* __restrict__ Wskip,
                                                    float* __restrict__ out) {
    __shared__ float sW[CIN * COUT];
    __shared__ float sx[32 * CIN];
    const int tid = threadIdx.x;
    const int r0 = blockIdx.x * 32;

    {
        const float4* W4 = (const float4*)Wskip;
        float4* sW4 = (float4*)sW;
        for (int e = tid; e < CIN * COUT / 4; e += 256) sW4[e] = W4[e];
        float4* sx4 = (float4*)sx;
        for (int e = tid; e < 32 * CIN / 4; e += 256) {
            int r = e >> 4, c4 = (e & 15) * 4;
            int row = r0 + r;
            sx4[e] = (row < NROWS) ? *(const float4*)(x + (size_t)row * CIN + c4)
                                   : make_float4(0.f, 0.f, 0.f, 0.f);
        }
    }
    __syncthreads();

    const int c = tid & 127, rh = tid >> 7;
    float id[16];
#pragma unroll
    for (int i = 0; i < 16; ++i) id[i] = 0.f;

#pragma unroll
    for (int kc = 0; kc < CIN / 8; ++kc) {
        float w[8];
#pragma unroll
        for (int i = 0; i < 8; ++i) w[i] = sW[(kc * 8 + i) * COUT + c];
#pragma unroll
        for (int rr = 0; rr < 16; ++rr) {
            int rl = rh * 16 + rr;
            float4 xa = *(const float4*)&sx[rl * CIN + kc * 8];
            float4 xb = *(const float4*)&sx[rl * CIN + kc * 8 + 4];
            float t = id[rr];
            t = fmaf(xa.x, w[0], t); t = fmaf(xa.y, w[1], t);
            t = fmaf(xa.z, w[2], t); t = fmaf(xa.w, w[3], t);
            t = fmaf(xb.x, w[4], t); t = fmaf(xb.y, w[5], t);
            t = fmaf(xb.z, w[6], t); t = fmaf(xb.w, w[7], t);
            id[rr] = t;
        }
    }

    const float A = g_bnA[1][c], B = g_bnB[1][c];
#pragma unroll
    for (int rr = 0; rr < 16; ++rr) {
        int row = r0 + rh * 16 + rr;
        if (row >= NROWS) continue;
        float v = g_h[(size_t)row * COUT + c];
        out[(size_t)row * COUT + c] = fmaxf(fmaf(v, A, B), 0.f) + id[rr];
    }
}

// ---------------- launch ----------------
extern "C" void kernel_launch(void* const* d_in, const int* in_sizes, int n_in,
                              void* d_out, int out_size) {
    const float* x      = (const float*)d_in[0];
    const int*   nbr    = (const int*)  d_in[1];
    const float* W1     = (const float*)d_in[2];
    const float* gamma1 = (const float*)d_in[3];
    const float* beta1  = (const float*)d_in[4];
    const float* W2     = (const float*)d_in[5];
    const float* gamma2 = (const float*)d_in[6];
    const float* beta2  = (const float*)d_in[7];
    const float* Wskip  = (const float*)d_in[8];
    float* out = (float*)d_out;

    cudaFuncSetAttribute(conv_mma_kernel<64>,  cudaFuncAttributeMaxDynamicSharedMemorySize, SM_TOT);
    cudaFuncSetAttribute(conv_mma_kernel<128>, cudaFuncAttributeMaxDynamicSharedMemorySize, SM_TOT);

    uint16_t* wt1; cudaGetSymbolAddress((void**)&wt1, g_Wt1);
    uint16_t* wt2; cudaGetSymbolAddress((void**)&wt2, g_Wt2);
    float* y;   cudaGetSymbolAddress((void**)&y,   g_y);
    float* h;   cudaGetSymbolAddress((void**)&h,   g_h);
    void*  x16; cudaGetSymbolAddress(&x16, g_x16);
    void*  h16; cudaGetSymbolAddress(&h16, g_h16);

    prep_kernel<64> <<<(KK * 64  * COUT + 255) / 256, 256>>>(W1);         // launch 1
    prep_kernel<128><<<(KK * 128 * COUT + 255) / 256, 256>>>(W2);         // launch 2
    x16_kernel<<<512, 256>>>(x);                                          // launch 3

    conv_mma_kernel<64><<<NBLK, 256, SM_TOT>>>((const __half*)x16, nbr, wt1, y);  // launch 4
    stats_mid_kernel<<<NPART, 128>>>();
    stats_final_kernel<<<1, 128>>>(0, gamma1, beta1);
    bn_apply16_kernel<<<1024, 256>>>();

    conv_mma_kernel<128><<<NBLK, 256, SM_TOT>>>((const __half*)h16, nbr, wt2, h);
    stats_mid_kernel<<<NPART, 128>>>();
    stats_final_kernel<<<1, 128>>>(1, gamma2, beta2);

    final_kernel<<<(NROWS + 31) / 32, 256>>>(x, Wskip, out);
}